// round 1
// baseline (speedup 1.0000x reference)
#include <cuda_runtime.h>
#include <math.h>

// ExpertsChooseMlp: 4-stage dense GEMM chain.
//  S1 dispatch: xd[b,e,c,d] = sum_t dm[b,t,e,c] * x[b,t,d]      (A K-major)
//  S2 fc1:      h[b,e,c,h'] = gelu(sum_d xd*w1[e,d,h'] + b1[e,h'])
//  S3 fc2:      y[b,e,c,o]  = sum_h h*w2[e,h,o]
//  S4 combine:  out[b,t,o]  = sum_{ec} comb[b,t,ec]*y[b,ec,o] + b2[o]

namespace {

constexpr int Bsz = 4, T = 2048, D = 512, E = 4, C = 1024, HE = 512, O = 512;

constexpr int BM = 128, BN = 128, BK = 8, TM = 8, TN = 8;
// threads per CTA = (BM/TM)*(BN/TN) = 256

// Scratch (allocation-free rule: __device__ globals)
__device__ float g_xd[(size_t)Bsz * E * C * D];   // 32 MB
__device__ float g_h [(size_t)Bsz * E * C * HE];  // 32 MB
__device__ float g_y [(size_t)Bsz * E * C * O];   // 32 MB

// EPI: 0 = none, 1 = bias + exact GELU, 2 = bias only
template <bool A_KMAJOR, int EPI>
__global__ __launch_bounds__(256, 1)
void sgemm_kernel(const float* __restrict__ Abase,
                  const float* __restrict__ Bbase,
                  float* __restrict__ Cbase,
                  const float* __restrict__ biasBase,
                  int M, int N, int K,
                  int lda, int ldb, int ldc,
                  int zdiv,
                  long Adiv, long Amod,
                  long Bdiv, long Bmod,
                  long Cdiv, long Cmod,
                  long BiasDiv, long BiasMod)
{
    const int z  = blockIdx.z;
    const int zq = z / zdiv;
    const int zr = z % zdiv;

    const float* A  = Abase + zq * Adiv + zr * Amod;
    const float* Bp = Bbase + zq * Bdiv + zr * Bmod;
    float*       Cp = Cbase + zq * Cdiv + zr * Cmod;
    const float* bias = (EPI >= 1) ? (biasBase + zq * BiasDiv + zr * BiasMod) : nullptr;

    __shared__ float As[BK][BM];
    __shared__ float Bs[BK][BN];

    const int tid  = threadIdx.x;
    const int crow = blockIdx.y * BM;   // M offset
    const int ccol = blockIdx.x * BN;   // N offset

    // K-major tile load indices (8 rows x 128 cols, float4)
    const int rowKB = tid / 32;          // 0..7
    const int colKB = (tid % 32) * 4;    // 0..124

    // M-major A tile load indices (128 rows x 8 cols, float4, transposed into smem)
    const int rowA = tid / 2;            // 0..127
    const int colA = (tid % 2) * 4;      // 0 or 4

    const int threadRow = (tid / (BN / TN)) * TM;  // 0..120 step 8
    const int threadCol = (tid % (BN / TN)) * TN;  // 0..120 step 8

    float acc[TM][TN];
    #pragma unroll
    for (int i = 0; i < TM; ++i)
        #pragma unroll
        for (int j = 0; j < TN; ++j) acc[i][j] = 0.0f;

    for (int k0 = 0; k0 < K; k0 += BK) {
        // ---- load A tile ----
        if (A_KMAJOR) {
            // A is [K, M] row-major: rows = k, contiguous in m
            float4 a = *reinterpret_cast<const float4*>(
                &A[(long)(k0 + rowKB) * lda + crow + colKB]);
            *reinterpret_cast<float4*>(&As[rowKB][colKB]) = a;
        } else {
            // A is [M, K] row-major: transpose into As[k][m]
            float4 a = *reinterpret_cast<const float4*>(
                &A[(long)(crow + rowA) * lda + k0 + colA]);
            As[colA + 0][rowA] = a.x;
            As[colA + 1][rowA] = a.y;
            As[colA + 2][rowA] = a.z;
            As[colA + 3][rowA] = a.w;
        }
        // ---- load B tile (always [K, N] row-major) ----
        {
            float4 b = *reinterpret_cast<const float4*>(
                &Bp[(long)(k0 + rowKB) * ldb + ccol + colKB]);
            *reinterpret_cast<float4*>(&Bs[rowKB][colKB]) = b;
        }
        __syncthreads();

        #pragma unroll
        for (int k = 0; k < BK; ++k) {
            float regM[TM], regN[TN];
            // vectorized smem reads (threadRow/threadCol are 8-aligned)
            *reinterpret_cast<float4*>(&regM[0]) =
                *reinterpret_cast<const float4*>(&As[k][threadRow]);
            *reinterpret_cast<float4*>(&regM[4]) =
                *reinterpret_cast<const float4*>(&As[k][threadRow + 4]);
            *reinterpret_cast<float4*>(&regN[0]) =
                *reinterpret_cast<const float4*>(&Bs[k][threadCol]);
            *reinterpret_cast<float4*>(&regN[4]) =
                *reinterpret_cast<const float4*>(&Bs[k][threadCol + 4]);
            #pragma unroll
            for (int i = 0; i < TM; ++i)
                #pragma unroll
                for (int j = 0; j < TN; ++j)
                    acc[i][j] = fmaf(regM[i], regN[j], acc[i][j]);
        }
        __syncthreads();
    }

    // ---- epilogue ----
    #pragma unroll
    for (int i = 0; i < TM; ++i) {
        const long r = crow + threadRow + i;
        #pragma unroll
        for (int j = 0; j < TN; j += 4) {
            float4 v;
            float* pv = &v.x;
            #pragma unroll
            for (int q = 0; q < 4; ++q) {
                float val = acc[i][j + q];
                if (EPI >= 1) val += bias[ccol + threadCol + j + q];
                if (EPI == 1) {
                    // exact GELU: 0.5*x*(1+erf(x/sqrt(2)))
                    val = 0.5f * val * (1.0f + erff(val * 0.70710678118654752f));
                }
                pv[q] = val;
            }
            *reinterpret_cast<float4*>(&Cp[r * ldc + ccol + threadCol + j]) = v;
        }
    }
}

} // namespace

extern "C" void kernel_launch(void* const* d_in, const int* in_sizes, int n_in,
                              void* d_out, int out_size)
{
    // metadata order: x, dispatch_mask, combine_array, w1, b1, w2, b2
    const float* x    = (const float*)d_in[0];
    const float* dm   = (const float*)d_in[1];
    const float* comb = (const float*)d_in[2];
    const float* w1   = (const float*)d_in[3];
    const float* b1   = (const float*)d_in[4];
    const float* w2   = (const float*)d_in[5];
    const float* b2   = (const float*)d_in[6];
    float* out = (float*)d_out;

    float* xd; cudaGetSymbolAddress((void**)&xd, g_xd);
    float* h;  cudaGetSymbolAddress((void**)&h,  g_h);
    float* y;  cudaGetSymbolAddress((void**)&y,  g_y);

    dim3 blk(256);

    // ---- Stage 1: dispatch GEMM (per (b,e) pair, A = dm K-major) ----
    // M=C=1024, N=D=512, K=T=2048
    {
        dim3 grid(D / BN, C / BM, Bsz * E);
        sgemm_kernel<true, 0><<<grid, blk>>>(
            dm, x, xd, nullptr,
            C, D, T,
            /*lda=*/E * C, /*ldb=*/D, /*ldc=*/D,
            /*zdiv=*/E,
            /*Adiv=*/(long)T * E * C, /*Amod=*/(long)C,
            /*Bdiv=*/(long)T * D,     /*Bmod=*/0,
            /*Cdiv=*/(long)E * C * D, /*Cmod=*/(long)C * D,
            0, 0);
    }

    // ---- Stage 2: fc1 + b1 + GELU (per (b,e)) ----
    // M=C=1024, N=HE=512, K=D=512
    {
        dim3 grid(HE / BN, C / BM, Bsz * E);
        sgemm_kernel<false, 1><<<grid, blk>>>(
            xd, w1, h, b1,
            C, HE, D,
            /*lda=*/D, /*ldb=*/HE, /*ldc=*/HE,
            /*zdiv=*/E,
            /*Adiv=*/(long)E * C * D,  /*Amod=*/(long)C * D,
            /*Bdiv=*/0,                /*Bmod=*/(long)D * HE,
            /*Cdiv=*/(long)E * C * HE, /*Cmod=*/(long)C * HE,
            /*BiasDiv=*/0,             /*BiasMod=*/(long)HE);
    }

    // ---- Stage 3: fc2 (per (b,e)) ----
    // M=C=1024, N=O=512, K=HE=512
    {
        dim3 grid(O / BN, C / BM, Bsz * E);
        sgemm_kernel<false, 0><<<grid, blk>>>(
            h, w2, y, nullptr,
            C, O, HE,
            /*lda=*/HE, /*ldb=*/O, /*ldc=*/O,
            /*zdiv=*/E,
            /*Adiv=*/(long)E * C * HE, /*Amod=*/(long)C * HE,
            /*Bdiv=*/0,                /*Bmod=*/(long)HE * O,
            /*Cdiv=*/(long)E * C * O,  /*Cmod=*/(long)C * O,
            0, 0);
    }

    // ---- Stage 4: combine GEMM + b2 (per b) ----
    // M=T=2048, N=O=512, K=E*C=4096
    {
        dim3 grid(O / BN, T / BM, Bsz);
        sgemm_kernel<false, 2><<<grid, blk>>>(
            comb, y, out, b2,
            T, O, E * C,
            /*lda=*/E * C, /*ldb=*/O, /*ldc=*/O,
            /*zdiv=*/1,
            /*Adiv=*/(long)T * E * C, /*Amod=*/0,
            /*Bdiv=*/(long)E * C * O, /*Bmod=*/0,
            /*Cdiv=*/(long)T * O,     /*Cmod=*/0,
            /*BiasDiv=*/0,            /*BiasMod=*/0);
    }
}

// round 2
// speedup vs baseline: 1.0041x; 1.0041x over previous
#include <cuda_runtime.h>
#include <math.h>

// ExpertsChooseMlp: 4-stage dense GEMM chain.
//  S1 dispatch: xd[b,e,c,d] = sum_t dm[b,t,e,c] * x[b,t,d]      (A K-major)
//  S2 fc1:      h[b,e,c,h'] = gelu(sum_d xd*w1[e,d,h'] + b1[e,h'])
//  S3 fc2:      y[b,e,c,o]  = sum_h h*w2[e,h,o]
//  S4 combine:  out[b,t,o]  = sum_{ec} comb[b,t,ec]*y[b,ec,o] + b2[o]

namespace {

constexpr int Bsz = 4, T = 2048, D = 512, E = 4, C = 1024, HE = 512, O = 512;

constexpr int BM = 128, BN = 128, BK = 8, TM = 8, TN = 8;
// threads per CTA = (BM/TM)*(BN/TN) = 256

// Scratch (allocation-free rule: __device__ globals)
__device__ float g_xd[(size_t)Bsz * E * C * D];   // 32 MB
__device__ float g_h [(size_t)Bsz * E * C * HE];  // 32 MB
__device__ float g_y [(size_t)Bsz * E * C * O];   // 32 MB

// EPI: 0 = none, 1 = bias + exact GELU, 2 = bias only
template <bool A_KMAJOR, int EPI>
__global__ __launch_bounds__(256, 1)
void sgemm_kernel(const float* __restrict__ Abase,
                  const float* __restrict__ Bbase,
                  float* __restrict__ Cbase,
                  const float* __restrict__ biasBase,
                  int M, int N, int K,
                  int lda, int ldb, int ldc,
                  int zdiv,
                  long Adiv, long Amod,
                  long Bdiv, long Bmod,
                  long Cdiv, long Cmod,
                  long BiasDiv, long BiasMod)
{
    const int z  = blockIdx.z;
    const int zq = z / zdiv;
    const int zr = z % zdiv;

    const float* A  = Abase + zq * Adiv + zr * Amod;
    const float* Bp = Bbase + zq * Bdiv + zr * Bmod;
    float*       Cp = Cbase + zq * Cdiv + zr * Cmod;
    const float* bias = (EPI >= 1) ? (biasBase + zq * BiasDiv + zr * BiasMod) : nullptr;

    __shared__ float As[BK][BM];
    __shared__ float Bs[BK][BN];

    const int tid  = threadIdx.x;
    const int crow = blockIdx.y * BM;   // M offset
    const int ccol = blockIdx.x * BN;   // N offset

    // K-major tile load indices (8 rows x 128 cols, float4)
    const int rowKB = tid / 32;          // 0..7
    const int colKB = (tid % 32) * 4;    // 0..124

    // M-major A tile load indices (128 rows x 8 cols, float4, transposed into smem)
    const int rowA = tid / 2;            // 0..127
    const int colA = (tid % 2) * 4;      // 0 or 4

    const int threadRow = (tid / (BN / TN)) * TM;  // 0..120 step 8
    const int threadCol = (tid % (BN / TN)) * TN;  // 0..120 step 8

    float acc[TM][TN];
    #pragma unroll
    for (int i = 0; i < TM; ++i)
        #pragma unroll
        for (int j = 0; j < TN; ++j) acc[i][j] = 0.0f;

    for (int k0 = 0; k0 < K; k0 += BK) {
        // ---- load A tile ----
        if (A_KMAJOR) {
            // A is [K, M] row-major: rows = k, contiguous in m
            float4 a = *reinterpret_cast<const float4*>(
                &A[(long)(k0 + rowKB) * lda + crow + colKB]);
            *reinterpret_cast<float4*>(&As[rowKB][colKB]) = a;
        } else {
            // A is [M, K] row-major: transpose into As[k][m]
            float4 a = *reinterpret_cast<const float4*>(
                &A[(long)(crow + rowA) * lda + k0 + colA]);
            As[colA + 0][rowA] = a.x;
            As[colA + 1][rowA] = a.y;
            As[colA + 2][rowA] = a.z;
            As[colA + 3][rowA] = a.w;
        }
        // ---- load B tile (always [K, N] row-major) ----
        {
            float4 b = *reinterpret_cast<const float4*>(
                &Bp[(long)(k0 + rowKB) * ldb + ccol + colKB]);
            *reinterpret_cast<float4*>(&Bs[rowKB][colKB]) = b;
        }
        __syncthreads();

        #pragma unroll
        for (int k = 0; k < BK; ++k) {
            float regM[TM], regN[TN];
            // vectorized smem reads (threadRow/threadCol are 8-aligned)
            *reinterpret_cast<float4*>(&regM[0]) =
                *reinterpret_cast<const float4*>(&As[k][threadRow]);
            *reinterpret_cast<float4*>(&regM[4]) =
                *reinterpret_cast<const float4*>(&As[k][threadRow + 4]);
            *reinterpret_cast<float4*>(&regN[0]) =
                *reinterpret_cast<const float4*>(&Bs[k][threadCol]);
            *reinterpret_cast<float4*>(&regN[4]) =
                *reinterpret_cast<const float4*>(&Bs[k][threadCol + 4]);
            #pragma unroll
            for (int i = 0; i < TM; ++i)
                #pragma unroll
                for (int j = 0; j < TN; ++j)
                    acc[i][j] = fmaf(regM[i], regN[j], acc[i][j]);
        }
        __syncthreads();
    }

    // ---- epilogue ----
    #pragma unroll
    for (int i = 0; i < TM; ++i) {
        const long r = crow + threadRow + i;
        #pragma unroll
        for (int j = 0; j < TN; j += 4) {
            float4 v;
            float* pv = &v.x;
            #pragma unroll
            for (int q = 0; q < 4; ++q) {
                float val = acc[i][j + q];
                if (EPI >= 1) val += bias[ccol + threadCol + j + q];
                if (EPI == 1) {
                    // exact GELU: 0.5*x*(1+erf(x/sqrt(2)))
                    val = 0.5f * val * (1.0f + erff(val * 0.70710678118654752f));
                }
                pv[q] = val;
            }
            *reinterpret_cast<float4*>(&Cp[r * ldc + ccol + threadCol + j]) = v;
        }
    }
}

} // namespace

extern "C" void kernel_launch(void* const* d_in, const int* in_sizes, int n_in,
                              void* d_out, int out_size)
{
    // metadata order: x, dispatch_mask, combine_array, w1, b1, w2, b2
    const float* x    = (const float*)d_in[0];
    const float* dm   = (const float*)d_in[1];
    const float* comb = (const float*)d_in[2];
    const float* w1   = (const float*)d_in[3];
    const float* b1   = (const float*)d_in[4];
    const float* w2   = (const float*)d_in[5];
    const float* b2   = (const float*)d_in[6];
    float* out = (float*)d_out;

    float* xd; cudaGetSymbolAddress((void**)&xd, g_xd);
    float* h;  cudaGetSymbolAddress((void**)&h,  g_h);
    float* y;  cudaGetSymbolAddress((void**)&y,  g_y);

    dim3 blk(256);

    // ---- Stage 1: dispatch GEMM (per (b,e) pair, A = dm K-major) ----
    // M=C=1024, N=D=512, K=T=2048
    {
        dim3 grid(D / BN, C / BM, Bsz * E);
        sgemm_kernel<true, 0><<<grid, blk>>>(
            dm, x, xd, nullptr,
            C, D, T,
            /*lda=*/E * C, /*ldb=*/D, /*ldc=*/D,
            /*zdiv=*/E,
            /*Adiv=*/(long)T * E * C, /*Amod=*/(long)C,
            /*Bdiv=*/(long)T * D,     /*Bmod=*/0,
            /*Cdiv=*/(long)E * C * D, /*Cmod=*/(long)C * D,
            0, 0);
    }

    // ---- Stage 2: fc1 + b1 + GELU (per (b,e)) ----
    // M=C=1024, N=HE=512, K=D=512
    {
        dim3 grid(HE / BN, C / BM, Bsz * E);
        sgemm_kernel<false, 1><<<grid, blk>>>(
            xd, w1, h, b1,
            C, HE, D,
            /*lda=*/D, /*ldb=*/HE, /*ldc=*/HE,
            /*zdiv=*/E,
            /*Adiv=*/(long)E * C * D,  /*Amod=*/(long)C * D,
            /*Bdiv=*/0,                /*Bmod=*/(long)D * HE,
            /*Cdiv=*/(long)E * C * HE, /*Cmod=*/(long)C * HE,
            /*BiasDiv=*/0,             /*BiasMod=*/(long)HE);
    }

    // ---- Stage 3: fc2 (per (b,e)) ----
    // M=C=1024, N=O=512, K=HE=512
    {
        dim3 grid(O / BN, C / BM, Bsz * E);
        sgemm_kernel<false, 0><<<grid, blk>>>(
            h, w2, y, nullptr,
            C, O, HE,
            /*lda=*/HE, /*ldb=*/O, /*ldc=*/O,
            /*zdiv=*/E,
            /*Adiv=*/(long)E * C * HE, /*Amod=*/(long)C * HE,
            /*Bdiv=*/0,                /*Bmod=*/(long)HE * O,
            /*Cdiv=*/(long)E * C * O,  /*Cmod=*/(long)C * O,
            0, 0);
    }

    // ---- Stage 4: combine GEMM + b2 (per b) ----
    // M=T=2048, N=O=512, K=E*C=4096
    {
        dim3 grid(O / BN, T / BM, Bsz);
        sgemm_kernel<false, 2><<<grid, blk>>>(
            comb, y, out, b2,
            T, O, E * C,
            /*lda=*/E * C, /*ldb=*/O, /*ldc=*/O,
            /*zdiv=*/1,
            /*Adiv=*/(long)T * E * C, /*Amod=*/0,
            /*Bdiv=*/(long)E * C * O, /*Bmod=*/0,
            /*Cdiv=*/(long)T * O,     /*Cmod=*/0,
            /*BiasDiv=*/0,            /*BiasMod=*/0);
    }
}

// round 4
// speedup vs baseline: 1.7087x; 1.7016x over previous
#include <cuda_runtime.h>
#include <cuda_bf16.h>
#include <math.h>

namespace {

constexpr int Bsz = 4, T = 2048, D = 512, E = 4, C = 1024, HE = 512, O = 512;
constexpr int STG = 4;
constexpr int SMEM_DYN = STG * 32768 + 1024;

// packed hi/lo bf16 scratch: row = [K/32 groups][32 hi | 32 lo]
__device__ __align__(256) unsigned short g_A1p[(size_t)Bsz*E*C*2*T];    // dm^T  [be][C][2T]
__device__ __align__(256) unsigned short g_B1p[(size_t)Bsz*D*2*T];      // x^T   [b][D][2T]
__device__ __align__(256) unsigned short g_B2p[(size_t)E*HE*2*D];       // w1^T  [e][HE][2D]
__device__ __align__(256) unsigned short g_B3p[(size_t)E*O*2*HE];       // w2^T  [e][O][2HE]
__device__ __align__(256) unsigned short g_A2p[(size_t)Bsz*E*C*2*D];    // xd    [be][C][2D]
__device__ __align__(256) unsigned short g_A3p[(size_t)Bsz*E*C*2*HE];   // h     [be][C][2HE]
__device__ __align__(256) float          g_y  [(size_t)Bsz*E*C*O];      // fp32 y
__device__ __align__(256) unsigned short g_B4p[(size_t)Bsz*O*2*E*C];    // y^T   [b][O][2EC]
__device__ __align__(256) unsigned short g_A4p[(size_t)Bsz*T*2*E*C];    // comb  [b*T][2EC]

__device__ __forceinline__ unsigned smem_u32(const void* p) {
    unsigned a;
    asm("{ .reg .u64 t; cvta.to.shared.u64 t, %1; cvt.u32.u64 %0, t; }" : "=r"(a) : "l"(p));
    return a;
}
__device__ __forceinline__ unsigned swz(unsigned o) { return o ^ ((o >> 3) & 0x70); }

__device__ __forceinline__ void split_bf(float v, __nv_bfloat16& h, __nv_bfloat16& l) {
    h = __float2bfloat16(v);
    l = __float2bfloat16(v - __bfloat162float(h));
}
__device__ __forceinline__ float gelu(float v) {
    return 0.5f * v * (1.0f + erff(v * 0.70710678118654752f));
}
__device__ __forceinline__ void cpa16(unsigned d, const void* s) {
    asm volatile("cp.async.cg.shared.global [%0], [%1], 16;" :: "r"(d), "l"(s) : "memory");
}
#define CP_COMMIT() asm volatile("cp.async.commit_group;" ::: "memory")
#define CP_WAIT2()  asm volatile("cp.async.wait_group 2;" ::: "memory")

#define LDSM_X4(R, addr) \
    asm volatile("ldmatrix.sync.aligned.m8n8.x4.shared.b16 {%0,%1,%2,%3}, [%4];" \
        : "=r"((R)[0]), "=r"((R)[1]), "=r"((R)[2]), "=r"((R)[3]) : "r"(addr))

#define MMA_BF16(Cc, Aa, Bb) \
    asm volatile("mma.sync.aligned.m16n8k16.row.col.f32.bf16.bf16.f32 " \
        "{%0,%1,%2,%3}, {%4,%5,%6,%7}, {%8,%9}, {%0,%1,%2,%3};" \
        : "+f"((Cc)[0]), "+f"((Cc)[1]), "+f"((Cc)[2]), "+f"((Cc)[3]) \
        : "r"((Aa)[0]), "r"((Aa)[1]), "r"((Aa)[2]), "r"((Aa)[3]), \
          "r"((Bb)[0]), "r"((Bb)[1]))

// ---------------- pack kernels ----------------
__global__ void pack_nt(const float* __restrict__ in, unsigned short* __restrict__ outRaw,
                        long n4, int Kdim) {
    long i = (long)blockIdx.x * blockDim.x + threadIdx.x;
    if (i >= n4) return;
    __nv_bfloat16* out = (__nv_bfloat16*)outRaw;
    long e = i * 4;
    long r = e / Kdim; int k = (int)(e % Kdim);
    float4 v = *(const float4*)(in + e);
    int g = k >> 5, j = k & 31;
    long base = (r * (long)(Kdim >> 5) + g) * 64;
    __nv_bfloat16 h0,h1,h2,h3,l0,l1,l2,l3;
    split_bf(v.x,h0,l0); split_bf(v.y,h1,l1); split_bf(v.z,h2,l2); split_bf(v.w,h3,l3);
    __nv_bfloat162 p;
    p.x=h0; p.y=h1; *(__nv_bfloat162*)(out + base + j)          = p;
    p.x=h2; p.y=h3; *(__nv_bfloat162*)(out + base + j + 2)      = p;
    p.x=l0; p.y=l1; *(__nv_bfloat162*)(out + base + 32 + j)     = p;
    p.x=l2; p.y=l3; *(__nv_bfloat162*)(out + base + 32 + j + 2) = p;
}

__global__ void pack_t(const float* __restrict__ inBase, unsigned short* __restrict__ outRaw,
                       int Kdim, int rs, long inZdiv, long inZmod, int zdiv, long outZ) {
    int z = blockIdx.z;
    const float* in = inBase + (long)(z / zdiv) * inZdiv + (long)(z % zdiv) * inZmod;
    __nv_bfloat16* out = (__nv_bfloat16*)outRaw + (long)z * outZ;
    __shared__ float t[32][33];
    int m0 = blockIdx.x * 32, k0 = blockIdx.y * 32;
    int tx = threadIdx.x, ty = threadIdx.y;  // 32 x 8
    #pragma unroll
    for (int i = 0; i < 4; ++i)
        t[ty + 8*i][tx] = in[(long)(k0 + ty + 8*i) * rs + m0 + tx];
    __syncthreads();
    #pragma unroll
    for (int i = 0; i < 4; ++i) {
        int r = ty + 8*i;
        long base = ((long)(m0 + r) * (Kdim >> 5) + (k0 >> 5)) * 64;
        int w = tx;
        int j = (w < 16) ? 2*w : 2*(w - 16);
        float v0 = t[j][r], v1 = t[j+1][r];
        __nv_bfloat16 a0,b0,a1,b1;
        split_bf(v0,a0,b0); split_bf(v1,a1,b1);
        __nv_bfloat162 p;
        if (w < 16) { p.x=a0; p.y=a1; *(__nv_bfloat162*)(out + base + 2*w) = p; }
        else        { p.x=b0; p.y=b1; *(__nv_bfloat162*)(out + base + 32 + 2*(w-16)) = p; }
    }
}

// ---------------- mma.sync hi/lo GEMM ----------------
// EPI: 0 = packed out; 1 = packed out + bias + GELU; 2 = fp32 out; 3 = fp32 out + bias
template <int EPI>
__global__ __launch_bounds__(256, 1)
void bgemm(const unsigned short* __restrict__ Ap,
           const unsigned short* __restrict__ Bp,
           void* __restrict__ Cout,
           const float* __restrict__ biasBase,
           int K, int Nn, int ldc,
           long Az, long Bz, long Cz, long biasZ, int bDiv)
{
    extern __shared__ char dynsm[];
    const unsigned smBase = (smem_u32(dynsm) + 1023u) & ~1023u;

    const int tid  = threadIdx.x;
    const int z    = blockIdx.z;
    const int bIdx = (z / bDiv) % E;
    const int crow = blockIdx.y * 128;
    const int ccol = blockIdx.x * 128;

    const int lane = tid & 31;
    const int warp = tid >> 5;
    const int wm   = warp & 3;   // 0..3 -> 32-row block
    const int wn   = warp >> 2;  // 0..1 -> 64-col block
    const int gid  = lane >> 2, tig = lane & 3;

    // ---- loader setup: threads 0-127 load A rows, 128-255 load B rows ----
    const int lrow = tid & 127;
    const unsigned short* grow;
    unsigned offs[8];
    {
        unsigned sOff;
        if (tid < 128) {
            grow = Ap + (long)z * Az + (long)(crow + lrow) * (2L * K);
            sOff = 0;
        } else {
            grow = Bp + (long)bIdx * Bz + (long)(ccol + lrow) * (2L * K);
            sOff = 16384;
        }
        #pragma unroll
        for (int c2 = 0; c2 < 8; ++c2)
            offs[c2] = sOff + swz((unsigned)(lrow * 128 + c2 * 16));
    }

    const int nch = K / 32;

    // prologue: stages 0..2
    #pragma unroll
    for (int s = 0; s < 3; ++s) {
        const char* src = (const char*)(grow + (long)s * 64);
        unsigned dst = smBase + s * 32768;
        #pragma unroll
        for (int c2 = 0; c2 < 8; ++c2) cpa16(dst + offs[c2], src + c2 * 16);
        CP_COMMIT();
    }

    float acc[2][8][4];
    #pragma unroll
    for (int a = 0; a < 2; ++a)
        #pragma unroll
        for (int b = 0; b < 8; ++b)
            #pragma unroll
            for (int q = 0; q < 4; ++q) acc[a][b][q] = 0.0f;

    for (int c = 0; c < nch; ++c) {
        CP_WAIT2();
        __syncthreads();

        // issue load for chunk c+3 into stage (c+3)&3
        if (c + 3 < nch) {
            const char* src = (const char*)(grow + (long)(c + 3) * 64);
            unsigned dst = smBase + ((c + 3) & 3) * 32768;
            #pragma unroll
            for (int c2 = 0; c2 < 8; ++c2) cpa16(dst + offs[c2], src + c2 * 16);
        }
        CP_COMMIT();

        // ---- compute chunk c from stage c&3 ----
        const unsigned aB = smBase + (c & 3) * 32768;
        const unsigned bB = aB + 16384;

        #pragma unroll
        for (int ks = 0; ks < 2; ++ks) {
            unsigned aH[2][4], aL[2][4], bH[4][4], bL[4][4];
            const int caH = ks * 2, caL = 4 + ks * 2;
            #pragma unroll
            for (int mt = 0; mt < 2; ++mt) {
                unsigned r = wm * 32 + mt * 16 + (lane & 15);
                unsigned ca = (unsigned)(lane >> 4);
                LDSM_X4(aH[mt], aB + swz(r * 128 + (caH + ca) * 16));
                LDSM_X4(aL[mt], aB + swz(r * 128 + (caL + ca) * 16));
            }
            #pragma unroll
            for (int p = 0; p < 4; ++p) {
                unsigned r = wn * 64 + p * 16 + (lane & 7) + ((lane >> 4) << 3);
                unsigned ca = (unsigned)((lane >> 3) & 1);
                LDSM_X4(bH[p], bB + swz(r * 128 + (caH + ca) * 16));
                LDSM_X4(bL[p], bB + swz(r * 128 + (caL + ca) * 16));
            }
            #pragma unroll
            for (int mt = 0; mt < 2; ++mt)
                #pragma unroll
                for (int p = 0; p < 4; ++p)
                    #pragma unroll
                    for (int s2 = 0; s2 < 2; ++s2) {
                        float* cc = acc[mt][p * 2 + s2];
                        MMA_BF16(cc, aH[mt], bH[p] + 2 * s2);  // hi*hi
                        MMA_BF16(cc, aH[mt], bL[p] + 2 * s2);  // hi*lo
                        MMA_BF16(cc, aL[mt], bH[p] + 2 * s2);  // lo*hi
                    }
        }
    }

    // ---- epilogue ----
    const float* bias = (EPI == 1 || EPI == 3) ? (biasBase + (long)bIdx * biasZ) : nullptr;

    #pragma unroll
    for (int mt = 0; mt < 2; ++mt) {
        #pragma unroll
        for (int half = 0; half < 2; ++half) {
            const int r = crow + wm * 32 + mt * 16 + gid + 8 * half;
            if (EPI <= 1) {
                unsigned short* dst = (unsigned short*)Cout + (long)z * Cz + (long)r * 2 * Nn;
                #pragma unroll
                for (int nj = 0; nj < 8; ++nj) {
                    const int cg = ccol + wn * 64 + nj * 8 + 2 * tig;
                    float v0 = acc[mt][nj][2 * half];
                    float v1 = acc[mt][nj][2 * half + 1];
                    if (EPI == 1) {
                        v0 = gelu(v0 + bias[cg]);
                        v1 = gelu(v1 + bias[cg + 1]);
                    }
                    __nv_bfloat16 h0, l0, h1, l1;
                    split_bf(v0, h0, l0); split_bf(v1, h1, l1);
                    __nv_bfloat162 ph; ph.x = h0; ph.y = h1;
                    __nv_bfloat162 pl; pl.x = l0; pl.y = l1;
                    long gb = (long)(cg >> 5) * 64 + (cg & 31);
                    *(__nv_bfloat162*)(dst + gb)      = ph;
                    *(__nv_bfloat162*)(dst + gb + 32) = pl;
                }
            } else {
                float* dst = (float*)Cout + (long)z * Cz + (long)r * ldc;
                #pragma unroll
                for (int nj = 0; nj < 8; ++nj) {
                    const int cg = ccol + wn * 64 + nj * 8 + 2 * tig;
                    float v0 = acc[mt][nj][2 * half];
                    float v1 = acc[mt][nj][2 * half + 1];
                    if (EPI == 3) { v0 += bias[cg]; v1 += bias[cg + 1]; }
                    float2 p; p.x = v0; p.y = v1;
                    *(float2*)(dst + cg) = p;
                }
            }
        }
    }
}

} // namespace

extern "C" void kernel_launch(void* const* d_in, const int* in_sizes, int n_in,
                              void* d_out, int out_size)
{
    const float* x    = (const float*)d_in[0];
    const float* dm   = (const float*)d_in[1];
    const float* comb = (const float*)d_in[2];
    const float* w1   = (const float*)d_in[3];
    const float* b1   = (const float*)d_in[4];
    const float* w2   = (const float*)d_in[5];
    const float* b2   = (const float*)d_in[6];
    float* out = (float*)d_out;

    unsigned short *A1p, *B1p, *B2p, *B3p, *A2p, *A3p, *B4p, *A4p;
    float* yscr;
    cudaGetSymbolAddress((void**)&A1p, g_A1p);
    cudaGetSymbolAddress((void**)&B1p, g_B1p);
    cudaGetSymbolAddress((void**)&B2p, g_B2p);
    cudaGetSymbolAddress((void**)&B3p, g_B3p);
    cudaGetSymbolAddress((void**)&A2p, g_A2p);
    cudaGetSymbolAddress((void**)&A3p, g_A3p);
    cudaGetSymbolAddress((void**)&B4p, g_B4p);
    cudaGetSymbolAddress((void**)&A4p, g_A4p);
    cudaGetSymbolAddress((void**)&yscr, g_y);

    cudaFuncSetAttribute(bgemm<0>, cudaFuncAttributeMaxDynamicSharedMemorySize, SMEM_DYN);
    cudaFuncSetAttribute(bgemm<1>, cudaFuncAttributeMaxDynamicSharedMemorySize, SMEM_DYN);
    cudaFuncSetAttribute(bgemm<2>, cudaFuncAttributeMaxDynamicSharedMemorySize, SMEM_DYN);
    cudaFuncSetAttribute(bgemm<3>, cudaFuncAttributeMaxDynamicSharedMemorySize, SMEM_DYN);

    dim3 pblk(32, 8);
    // dm^T -> A1p : per (b,e), out [C][T]
    pack_t<<<dim3(C/32, T/32, Bsz*E), pblk>>>(dm, A1p, T, E*C,
        (long)T*E*C, (long)C, E, (long)C*2*T);
    // x^T -> B1p : per b, out [D][T]
    pack_t<<<dim3(D/32, T/32, Bsz), pblk>>>(x, B1p, T, D,
        (long)T*D, 0L, 1, (long)D*2*T);
    // w1^T -> B2p : per e, out [HE][D]
    pack_t<<<dim3(HE/32, D/32, E), pblk>>>(w1, B2p, D, HE,
        (long)D*HE, 0L, 1, (long)HE*2*D);
    // w2^T -> B3p : per e, out [O][HE]
    pack_t<<<dim3(O/32, HE/32, E), pblk>>>(w2, B3p, HE, O,
        (long)HE*O, 0L, 1, (long)O*2*HE);
    // comb -> A4p : flat [B*T][E*C]
    {
        long n4 = (long)Bsz * T * E * C / 4;
        pack_nt<<<(unsigned)(n4 / 256), 256>>>(comb, A4p, n4, E*C);
    }

    // S1: xd = dm^T * x  (M=C, N=D, K=T) packed -> A2p
    bgemm<0><<<dim3(D/128, C/128, Bsz*E), 256, SMEM_DYN>>>(
        A1p, B1p, A2p, nullptr, T, D, D,
        (long)C*2*T, (long)D*2*T, (long)C*2*D, 0L, 4);
    // S2: h = gelu(xd*w1 + b1)  (K=D) packed -> A3p
    bgemm<1><<<dim3(HE/128, C/128, Bsz*E), 256, SMEM_DYN>>>(
        A2p, B2p, A3p, b1, D, HE, HE,
        (long)C*2*D, (long)HE*2*D, (long)C*2*HE, (long)HE, 1);
    // S3: y = h*w2  (K=HE) fp32 -> yscr
    bgemm<2><<<dim3(O/128, C/128, Bsz*E), 256, SMEM_DYN>>>(
        A3p, B3p, yscr, nullptr, HE, O, O,
        (long)C*2*HE, (long)O*2*HE, (long)C*O, 0L, 1);
    // y^T -> B4p : per b, out [O][E*C]
    pack_t<<<dim3(O/32, (E*C)/32, Bsz), pblk>>>(yscr, B4p, E*C, O,
        (long)E*C*O, 0L, 1, (long)O*2*E*C);
    // S4: out = comb * y^T + b2  (M=T, N=O, K=E*C) fp32 out
    bgemm<3><<<dim3(O/128, T/128, Bsz), 256, SMEM_DYN>>>(
        A4p, B4p, out, b2, E*C, O, O,
        (long)T*2*E*C, (long)O*2*E*C, (long)T*O, 0L, 1);
}

// round 5
// speedup vs baseline: 1.8957x; 1.1094x over previous
#include <cuda_runtime.h>
#include <cuda_bf16.h>
#include <math.h>

namespace {

constexpr int Bsz = 4, T = 2048, D = 512, E = 4, C = 1024, HE = 512, O = 512;
constexpr int STG = 4;
constexpr int STAGE_BYTES = 49152;               // 16KB A + 32KB B
constexpr int SMEM_DYN = STG * STAGE_BYTES + 1024;

// packed hi/lo bf16 scratch: row = [K/32 groups][32 hi | 32 lo]
__device__ __align__(256) unsigned short g_A1p[(size_t)Bsz*E*C*2*T];    // dm^T  [be][C][2T]
__device__ __align__(256) unsigned short g_B1p[(size_t)Bsz*D*2*T];      // x^T   [b][D][2T]
__device__ __align__(256) unsigned short g_B2p[(size_t)E*HE*2*D];       // w1^T  [e][HE][2D]
__device__ __align__(256) unsigned short g_B3p[(size_t)E*O*2*HE];       // w2^T  [e][O][2HE]
__device__ __align__(256) unsigned short g_A2p[(size_t)Bsz*E*C*2*D];    // xd    [be][C][2D]
__device__ __align__(256) unsigned short g_A3p[(size_t)Bsz*E*C*2*HE];   // h     [be][C][2HE]
__device__ __align__(256) float          g_y  [(size_t)Bsz*E*C*O];      // fp32 y
__device__ __align__(256) unsigned short g_B4p[(size_t)Bsz*O*2*E*C];    // y^T   [b][O][2EC]
__device__ __align__(256) unsigned short g_A4p[(size_t)Bsz*T*2*E*C];    // comb  [b*T][2EC]

__device__ __forceinline__ unsigned smem_u32(const void* p) {
    unsigned a;
    asm("{ .reg .u64 t; cvta.to.shared.u64 t, %1; cvt.u32.u64 %0, t; }" : "=r"(a) : "l"(p));
    return a;
}
__device__ __forceinline__ unsigned swz(unsigned o) { return o ^ ((o >> 3) & 0x70); }

__device__ __forceinline__ void split_bf(float v, __nv_bfloat16& h, __nv_bfloat16& l) {
    h = __float2bfloat16(v);
    l = __float2bfloat16(v - __bfloat162float(h));
}
__device__ __forceinline__ float gelu(float v) {
    return 0.5f * v * (1.0f + erff(v * 0.70710678118654752f));
}
__device__ __forceinline__ void cpa16(unsigned d, const void* s) {
    asm volatile("cp.async.cg.shared.global [%0], [%1], 16;" :: "r"(d), "l"(s) : "memory");
}
#define CP_COMMIT() asm volatile("cp.async.commit_group;" ::: "memory")
#define CP_WAIT2()  asm volatile("cp.async.wait_group 2;" ::: "memory")

#define LDSM_X4(R, addr) \
    asm volatile("ldmatrix.sync.aligned.m8n8.x4.shared.b16 {%0,%1,%2,%3}, [%4];" \
        : "=r"((R)[0]), "=r"((R)[1]), "=r"((R)[2]), "=r"((R)[3]) : "r"(addr))

#define MMA_BF16(Cc, Aa, Bb) \
    asm volatile("mma.sync.aligned.m16n8k16.row.col.f32.bf16.bf16.f32 " \
        "{%0,%1,%2,%3}, {%4,%5,%6,%7}, {%8,%9}, {%0,%1,%2,%3};" \
        : "+f"((Cc)[0]), "+f"((Cc)[1]), "+f"((Cc)[2]), "+f"((Cc)[3]) \
        : "r"((Aa)[0]), "r"((Aa)[1]), "r"((Aa)[2]), "r"((Aa)[3]), \
          "r"((Bb)[0]), "r"((Bb)[1]))

// ---------------- pack kernels ----------------
__global__ void pack_nt(const float* __restrict__ in, unsigned short* __restrict__ outRaw,
                        long n4, int Kdim) {
    long i = (long)blockIdx.x * blockDim.x + threadIdx.x;
    if (i >= n4) return;
    __nv_bfloat16* out = (__nv_bfloat16*)outRaw;
    long e = i * 4;
    long r = e / Kdim; int k = (int)(e % Kdim);
    float4 v = *(const float4*)(in + e);
    int g = k >> 5, j = k & 31;
    long base = (r * (long)(Kdim >> 5) + g) * 64;
    __nv_bfloat16 h0,h1,h2,h3,l0,l1,l2,l3;
    split_bf(v.x,h0,l0); split_bf(v.y,h1,l1); split_bf(v.z,h2,l2); split_bf(v.w,h3,l3);
    __nv_bfloat162 p;
    p.x=h0; p.y=h1; *(__nv_bfloat162*)(out + base + j)          = p;
    p.x=h2; p.y=h3; *(__nv_bfloat162*)(out + base + j + 2)      = p;
    p.x=l0; p.y=l1; *(__nv_bfloat162*)(out + base + 32 + j)     = p;
    p.x=l2; p.y=l3; *(__nv_bfloat162*)(out + base + 32 + j + 2) = p;
}

__global__ void pack_t(const float* __restrict__ inBase, unsigned short* __restrict__ outRaw,
                       int Kdim, int rs, long inZdiv, long inZmod, int zdiv, long outZ) {
    int z = blockIdx.z;
    const float* in = inBase + (long)(z / zdiv) * inZdiv + (long)(z % zdiv) * inZmod;
    __nv_bfloat16* out = (__nv_bfloat16*)outRaw + (long)z * outZ;
    __shared__ float t[32][33];
    int m0 = blockIdx.x * 32, k0 = blockIdx.y * 32;
    int tx = threadIdx.x, ty = threadIdx.y;  // 32 x 8
    #pragma unroll
    for (int i = 0; i < 4; ++i)
        t[ty + 8*i][tx] = in[(long)(k0 + ty + 8*i) * rs + m0 + tx];
    __syncthreads();
    #pragma unroll
    for (int i = 0; i < 4; ++i) {
        int r = ty + 8*i;
        long base = ((long)(m0 + r) * (Kdim >> 5) + (k0 >> 5)) * 64;
        int w = tx;
        int j = (w < 16) ? 2*w : 2*(w - 16);
        float v0 = t[j][r], v1 = t[j+1][r];
        __nv_bfloat16 a0,b0,a1,b1;
        split_bf(v0,a0,b0); split_bf(v1,a1,b1);
        __nv_bfloat162 p;
        if (w < 16) { p.x=a0; p.y=a1; *(__nv_bfloat162*)(out + base + 2*w) = p; }
        else        { p.x=b0; p.y=b1; *(__nv_bfloat162*)(out + base + 32 + 2*(w-16)) = p; }
    }
}

// ---------------- mma.sync hi/lo GEMM, CTA 128x256, warp 64x64 ----------------
// EPI: 0 = packed out; 1 = packed out + bias + GELU; 2 = fp32 out; 3 = fp32 out + bias
template <int EPI>
__global__ __launch_bounds__(256, 1)
void bgemm(const unsigned short* __restrict__ Ap,
           const unsigned short* __restrict__ Bp,
           void* __restrict__ Cout,
           const float* __restrict__ biasBase,
           int K, int Nn, int ldc,
           long Az, long Bz, long Cz, long biasZ, int bDiv)
{
    extern __shared__ char dynsm[];
    const unsigned smBase = (smem_u32(dynsm) + 1023u) & ~1023u;

    const int tid  = threadIdx.x;
    const int z    = blockIdx.z;
    const int bIdx = (z / bDiv) % E;
    const int crow = blockIdx.y * 128;
    const int ccol = blockIdx.x * 256;

    const int lane = tid & 31;
    const int warp = tid >> 5;
    const int wm   = warp & 1;   // 0..1 -> 64-row block
    const int wn   = warp >> 1;  // 0..3 -> 64-col block
    const int gid  = lane >> 2, tig = lane & 3;

    // loaders: A rows by t<128 (rows 0..127), B rows by all 256 threads (rows 0..255)
    const unsigned short* growA =
        Ap + (long)z * Az + (long)(crow + (tid & 127)) * (2L * K);
    const unsigned short* growB =
        Bp + (long)bIdx * Bz + (long)(ccol + tid) * (2L * K);
    const unsigned aLOff = (unsigned)((tid & 127) * 128);
    const unsigned bLOff = 16384u + (unsigned)(tid * 128);

    const int nch = K / 32;

    // prologue: stages 0..2
    #pragma unroll
    for (int s = 0; s < 3; ++s) {
        unsigned stg = smBase + s * STAGE_BYTES;
        if (tid < 128) {
            const char* srcA = (const char*)(growA + (long)s * 64);
            #pragma unroll
            for (int c2 = 0; c2 < 8; ++c2)
                cpa16(stg + swz(aLOff + c2 * 16), srcA + c2 * 16);
        }
        {
            const char* srcB = (const char*)(growB + (long)s * 64);
            #pragma unroll
            for (int c2 = 0; c2 < 8; ++c2)
                cpa16(stg + swz(bLOff + c2 * 16) + ((bLOff >> 10) & ~0u) * 0, srcB + c2 * 16);
        }
        CP_COMMIT();
    }

    float acc[4][8][4];
    #pragma unroll
    for (int a = 0; a < 4; ++a)
        #pragma unroll
        for (int b = 0; b < 8; ++b)
            #pragma unroll
            for (int q = 0; q < 4; ++q) acc[a][b][q] = 0.0f;

    for (int c = 0; c < nch; ++c) {
        CP_WAIT2();
        __syncthreads();

        if (c + 3 < nch) {
            unsigned stg = smBase + ((c + 3) & 3) * STAGE_BYTES;
            if (tid < 128) {
                const char* srcA = (const char*)(growA + (long)(c + 3) * 64);
                #pragma unroll
                for (int c2 = 0; c2 < 8; ++c2)
                    cpa16(stg + swz(aLOff + c2 * 16), srcA + c2 * 16);
            }
            const char* srcB = (const char*)(growB + (long)(c + 3) * 64);
            #pragma unroll
            for (int c2 = 0; c2 < 8; ++c2)
                cpa16(stg + swz(bLOff + c2 * 16), srcB + c2 * 16);
        }
        CP_COMMIT();

        const unsigned aB = smBase + (c & 3) * STAGE_BYTES;
        const unsigned bB = aB + 16384;

        #pragma unroll
        for (int ks = 0; ks < 2; ++ks) {
            const int caH = ks * 2, caL = 4 + ks * 2;
            unsigned aH[4][4], aL[4][4];
            #pragma unroll
            for (int mt = 0; mt < 4; ++mt) {
                unsigned r = wm * 64 + mt * 16 + (lane & 15);
                unsigned ca = (unsigned)(lane >> 4);
                LDSM_X4(aH[mt], aB + swz(r * 128 + (caH + ca) * 16));
                LDSM_X4(aL[mt], aB + swz(r * 128 + (caL + ca) * 16));
            }
            #pragma unroll
            for (int p = 0; p < 4; ++p) {
                unsigned bH[4], bL[4];
                unsigned r = wn * 64 + p * 16 + (lane & 7) + ((lane >> 4) << 3);
                unsigned ca = (unsigned)((lane >> 3) & 1);
                LDSM_X4(bH, bB + swz(r * 128 + (caH + ca) * 16));
                LDSM_X4(bL, bB + swz(r * 128 + (caL + ca) * 16));
                #pragma unroll
                for (int mt = 0; mt < 4; ++mt)
                    #pragma unroll
                    for (int s2 = 0; s2 < 2; ++s2) {
                        float* cc = acc[mt][p * 2 + s2];
                        MMA_BF16(cc, aH[mt], bH + 2 * s2);  // hi*hi
                        MMA_BF16(cc, aH[mt], bL + 2 * s2);  // hi*lo
                        MMA_BF16(cc, aL[mt], bH + 2 * s2);  // lo*hi
                    }
            }
        }
    }

    // ---- epilogue ----
    const float* bias = (EPI == 1 || EPI == 3) ? (biasBase + (long)bIdx * biasZ) : nullptr;

    #pragma unroll
    for (int mt = 0; mt < 4; ++mt) {
        #pragma unroll
        for (int half = 0; half < 2; ++half) {
            const int r = crow + wm * 64 + mt * 16 + gid + 8 * half;
            if (EPI <= 1) {
                unsigned short* dst = (unsigned short*)Cout + (long)z * Cz + (long)r * 2 * Nn;
                #pragma unroll
                for (int nj = 0; nj < 8; ++nj) {
                    const int cg = ccol + wn * 64 + nj * 8 + 2 * tig;
                    float v0 = acc[mt][nj][2 * half];
                    float v1 = acc[mt][nj][2 * half + 1];
                    if (EPI == 1) {
                        v0 = gelu(v0 + bias[cg]);
                        v1 = gelu(v1 + bias[cg + 1]);
                    }
                    __nv_bfloat16 h0, l0, h1, l1;
                    split_bf(v0, h0, l0); split_bf(v1, h1, l1);
                    __nv_bfloat162 ph; ph.x = h0; ph.y = h1;
                    __nv_bfloat162 pl; pl.x = l0; pl.y = l1;
                    long gb = (long)(cg >> 5) * 64 + (cg & 31);
                    *(__nv_bfloat162*)(dst + gb)      = ph;
                    *(__nv_bfloat162*)(dst + gb + 32) = pl;
                }
            } else {
                float* dst = (float*)Cout + (long)z * Cz + (long)r * ldc;
                #pragma unroll
                for (int nj = 0; nj < 8; ++nj) {
                    const int cg = ccol + wn * 64 + nj * 8 + 2 * tig;
                    float v0 = acc[mt][nj][2 * half];
                    float v1 = acc[mt][nj][2 * half + 1];
                    if (EPI == 3) { v0 += bias[cg]; v1 += bias[cg + 1]; }
                    float2 p; p.x = v0; p.y = v1;
                    *(float2*)(dst + cg) = p;
                }
            }
        }
    }
}

} // namespace

extern "C" void kernel_launch(void* const* d_in, const int* in_sizes, int n_in,
                              void* d_out, int out_size)
{
    const float* x    = (const float*)d_in[0];
    const float* dm   = (const float*)d_in[1];
    const float* comb = (const float*)d_in[2];
    const float* w1   = (const float*)d_in[3];
    const float* b1   = (const float*)d_in[4];
    const float* w2   = (const float*)d_in[5];
    const float* b2   = (const float*)d_in[6];
    float* out = (float*)d_out;

    unsigned short *A1p, *B1p, *B2p, *B3p, *A2p, *A3p, *B4p, *A4p;
    float* yscr;
    cudaGetSymbolAddress((void**)&A1p, g_A1p);
    cudaGetSymbolAddress((void**)&B1p, g_B1p);
    cudaGetSymbolAddress((void**)&B2p, g_B2p);
    cudaGetSymbolAddress((void**)&B3p, g_B3p);
    cudaGetSymbolAddress((void**)&A2p, g_A2p);
    cudaGetSymbolAddress((void**)&A3p, g_A3p);
    cudaGetSymbolAddress((void**)&B4p, g_B4p);
    cudaGetSymbolAddress((void**)&A4p, g_A4p);
    cudaGetSymbolAddress((void**)&yscr, g_y);

    cudaFuncSetAttribute(bgemm<0>, cudaFuncAttributeMaxDynamicSharedMemorySize, SMEM_DYN);
    cudaFuncSetAttribute(bgemm<1>, cudaFuncAttributeMaxDynamicSharedMemorySize, SMEM_DYN);
    cudaFuncSetAttribute(bgemm<2>, cudaFuncAttributeMaxDynamicSharedMemorySize, SMEM_DYN);
    cudaFuncSetAttribute(bgemm<3>, cudaFuncAttributeMaxDynamicSharedMemorySize, SMEM_DYN);

    dim3 pblk(32, 8);
    // dm^T -> A1p : per (b,e), out [C][T]
    pack_t<<<dim3(C/32, T/32, Bsz*E), pblk>>>(dm, A1p, T, E*C,
        (long)T*E*C, (long)C, E, (long)C*2*T);
    // x^T -> B1p : per b, out [D][T]
    pack_t<<<dim3(D/32, T/32, Bsz), pblk>>>(x, B1p, T, D,
        (long)T*D, 0L, 1, (long)D*2*T);
    // w1^T -> B2p : per e, out [HE][D]
    pack_t<<<dim3(HE/32, D/32, E), pblk>>>(w1, B2p, D, HE,
        (long)D*HE, 0L, 1, (long)HE*2*D);
    // w2^T -> B3p : per e, out [O][HE]
    pack_t<<<dim3(O/32, HE/32, E), pblk>>>(w2, B3p, HE, O,
        (long)HE*O, 0L, 1, (long)O*2*HE);
    // comb -> A4p : flat [B*T][E*C]
    {
        long n4 = (long)Bsz * T * E * C / 4;
        pack_nt<<<(unsigned)(n4 / 256), 256>>>(comb, A4p, n4, E*C);
    }

    // S1: xd = dm^T * x  (M=C, N=D, K=T) packed -> A2p
    bgemm<0><<<dim3(D/256, C/128, Bsz*E), 256, SMEM_DYN>>>(
        A1p, B1p, A2p, nullptr, T, D, D,
        (long)C*2*T, (long)D*2*T, (long)C*2*D, 0L, 4);
    // S2: h = gelu(xd*w1 + b1)  (K=D) packed -> A3p
    bgemm<1><<<dim3(HE/256, C/128, Bsz*E), 256, SMEM_DYN>>>(
        A2p, B2p, A3p, b1, D, HE, HE,
        (long)C*2*D, (long)HE*2*D, (long)C*2*HE, (long)HE, 1);
    // S3: y = h*w2  (K=HE) fp32 -> yscr
    bgemm<2><<<dim3(O/256, C/128, Bsz*E), 256, SMEM_DYN>>>(
        A3p, B3p, yscr, nullptr, HE, O, O,
        (long)C*2*HE, (long)O*2*HE, (long)C*O, 0L, 1);
    // y^T -> B4p : per b, out [O][E*C]
    pack_t<<<dim3(O/32, (E*C)/32, Bsz), pblk>>>(yscr, B4p, E*C, O,
        (long)E*C*O, 0L, 1, (long)O*2*E*C);
    // S4: out = comb * y^T + b2  (M=T, N=O, K=E*C) fp32 out
    bgemm<3><<<dim3(O/256, T/128, Bsz), 256, SMEM_DYN>>>(
        A4p, B4p, out, b2, E*C, O, O,
        (long)T*2*E*C, (long)O*2*E*C, (long)T*O, 0L, 1);
}

// round 6
// speedup vs baseline: 2.2968x; 1.2116x over previous
#include <cuda_runtime.h>
#include <cuda_fp16.h>
#include <math.h>

namespace {

constexpr int Bsz = 4, T = 2048, D = 512, E = 4, C = 1024, HE = 512, O = 512;
constexpr int STG = 4;
constexpr int STAGE_BYTES = 49152;               // 16KB A + 32KB B
constexpr int SMEM_DYN = STG * STAGE_BYTES + 1024;

// packed hi/lo fp16 scratch: row = [K/32 groups][32 hi | 32 lo]
__device__ __align__(256) unsigned short g_A1p[(size_t)Bsz*E*C*2*T];    // dm^T  [be][C][2T]
__device__ __align__(256) unsigned short g_B1p[(size_t)Bsz*D*2*T];      // x^T   [b][D][2T]
__device__ __align__(256) unsigned short g_B2p[(size_t)E*HE*2*D];       // w1^T  [e][HE][2D]
__device__ __align__(256) unsigned short g_B3p[(size_t)E*O*2*HE];       // w2^T  [e][O][2HE]
__device__ __align__(256) unsigned short g_A2p[(size_t)Bsz*E*C*2*D];    // xd    [be][C][2D]
__device__ __align__(256) unsigned short g_A3p[(size_t)Bsz*E*C*2*HE];   // h     [be][C][2HE]
__device__ __align__(256) float          g_y  [(size_t)Bsz*E*C*O];      // fp32 y
__device__ __align__(256) unsigned short g_B4p[(size_t)Bsz*O*2*E*C];    // y^T   [b][O][2EC]
__device__ __align__(256) unsigned short g_A4p[(size_t)Bsz*T*2*E*C];    // comb  [b*T][2EC]

__device__ __forceinline__ unsigned smem_u32(const void* p) {
    unsigned a;
    asm("{ .reg .u64 t; cvta.to.shared.u64 t, %1; cvt.u32.u64 %0, t; }" : "=r"(a) : "l"(p));
    return a;
}
__device__ __forceinline__ unsigned swz(unsigned o) { return o ^ ((o >> 3) & 0x70); }

__device__ __forceinline__ void split_h(float v, __half& h, __half& l) {
    h = __float2half_rn(v);
    l = __float2half_rn(v - __half2float(h));
}
__device__ __forceinline__ float gelu(float v) {
    return 0.5f * v * (1.0f + erff(v * 0.70710678118654752f));
}
__device__ __forceinline__ void cpa16(unsigned d, const void* s) {
    asm volatile("cp.async.cg.shared.global [%0], [%1], 16;" :: "r"(d), "l"(s) : "memory");
}
#define CP_COMMIT() asm volatile("cp.async.commit_group;" ::: "memory")
#define CP_WAIT2()  asm volatile("cp.async.wait_group 2;" ::: "memory")

#define LDSM_X4(R, addr) \
    asm volatile("ldmatrix.sync.aligned.m8n8.x4.shared.b16 {%0,%1,%2,%3}, [%4];" \
        : "=r"((R)[0]), "=r"((R)[1]), "=r"((R)[2]), "=r"((R)[3]) : "r"(addr))

#define MMA_F16(Cc, Aa, Bb) \
    asm volatile("mma.sync.aligned.m16n8k16.row.col.f32.f16.f16.f32 " \
        "{%0,%1,%2,%3}, {%4,%5,%6,%7}, {%8,%9}, {%0,%1,%2,%3};" \
        : "+f"((Cc)[0]), "+f"((Cc)[1]), "+f"((Cc)[2]), "+f"((Cc)[3]) \
        : "r"((Aa)[0]), "r"((Aa)[1]), "r"((Aa)[2]), "r"((Aa)[3]), \
          "r"((Bb)[0]), "r"((Bb)[1]))

// ---------------- pack kernels ----------------
__global__ void pack_nt(const float* __restrict__ in, unsigned short* __restrict__ outRaw,
                        long n4, int Kdim) {
    long i = (long)blockIdx.x * blockDim.x + threadIdx.x;
    if (i >= n4) return;
    __half* out = (__half*)outRaw;
    long e = i * 4;
    long r = e / Kdim; int k = (int)(e % Kdim);
    float4 v = *(const float4*)(in + e);
    int g = k >> 5, j = k & 31;
    long base = (r * (long)(Kdim >> 5) + g) * 64;
    __half h0,h1,h2,h3,l0,l1,l2,l3;
    split_h(v.x,h0,l0); split_h(v.y,h1,l1); split_h(v.z,h2,l2); split_h(v.w,h3,l3);
    __half2 p;
    p.x=h0; p.y=h1; *(__half2*)(out + base + j)          = p;
    p.x=h2; p.y=h3; *(__half2*)(out + base + j + 2)      = p;
    p.x=l0; p.y=l1; *(__half2*)(out + base + 32 + j)     = p;
    p.x=l2; p.y=l3; *(__half2*)(out + base + 32 + j + 2) = p;
}

__global__ void pack_t(const float* __restrict__ inBase, unsigned short* __restrict__ outRaw,
                       int Kdim, int rs, long inZdiv, long inZmod, int zdiv, long outZ) {
    int z = blockIdx.z;
    const float* in = inBase + (long)(z / zdiv) * inZdiv + (long)(z % zdiv) * inZmod;
    __half* out = (__half*)outRaw + (long)z * outZ;
    __shared__ float t[32][33];
    int m0 = blockIdx.x * 32, k0 = blockIdx.y * 32;
    int tx = threadIdx.x, ty = threadIdx.y;  // 32 x 8
    #pragma unroll
    for (int i = 0; i < 4; ++i)
        t[ty + 8*i][tx] = in[(long)(k0 + ty + 8*i) * rs + m0 + tx];
    __syncthreads();
    #pragma unroll
    for (int i = 0; i < 4; ++i) {
        int r = ty + 8*i;
        long base = ((long)(m0 + r) * (Kdim >> 5) + (k0 >> 5)) * 64;
        int w = tx;
        int j = (w < 16) ? 2*w : 2*(w - 16);
        float v0 = t[j][r], v1 = t[j+1][r];
        __half a0,b0,a1,b1;
        split_h(v0,a0,b0); split_h(v1,a1,b1);
        __half2 p;
        if (w < 16) { p.x=a0; p.y=a1; *(__half2*)(out + base + 2*w) = p; }
        else        { p.x=b0; p.y=b1; *(__half2*)(out + base + 32 + 2*(w-16)) = p; }
    }
}

// ------- mma.sync fp16 2-term GEMM, CTA 128x256, warp 64x64 -------
// C = A_hi*B_hi + A_lo*B_hi  (= A * B_hi exactly; error = A*B_lo ~ 2^-12)
// EPI: 0 = packed out; 1 = packed out + bias + GELU; 2 = fp32 out; 3 = fp32 out + bias
template <int EPI>
__global__ __launch_bounds__(256, 1)
void bgemm(const unsigned short* __restrict__ Ap,
           const unsigned short* __restrict__ Bp,
           void* __restrict__ Cout,
           const float* __restrict__ biasBase,
           int K, int Nn, int ldc,
           long Az, long Bz, long Cz, long biasZ, int bDiv)
{
    extern __shared__ char dynsm[];
    const unsigned smBase = (smem_u32(dynsm) + 1023u) & ~1023u;

    const int tid  = threadIdx.x;
    const int z    = blockIdx.z;
    const int bIdx = (z / bDiv) % E;
    const int crow = blockIdx.y * 128;
    const int ccol = blockIdx.x * 256;

    const int lane = tid & 31;
    const int warp = tid >> 5;
    const int wm   = warp & 1;   // 0..1 -> 64-row block
    const int wn   = warp >> 1;  // 0..3 -> 64-col block
    const int gid  = lane >> 2, tig = lane & 3;

    const unsigned short* growA =
        Ap + (long)z * Az + (long)(crow + (tid & 127)) * (2L * K);
    const unsigned short* growB =
        Bp + (long)bIdx * Bz + (long)(ccol + tid) * (2L * K);
    const unsigned aLOff = (unsigned)((tid & 127) * 128);
    const unsigned bLOff = 16384u + (unsigned)(tid * 128);

    const int nch = K / 32;

    #pragma unroll
    for (int s = 0; s < 3; ++s) {
        unsigned stg = smBase + s * STAGE_BYTES;
        if (tid < 128) {
            const char* srcA = (const char*)(growA + (long)s * 64);
            #pragma unroll
            for (int c2 = 0; c2 < 8; ++c2)
                cpa16(stg + swz(aLOff + c2 * 16), srcA + c2 * 16);
        }
        {
            const char* srcB = (const char*)(growB + (long)s * 64);
            #pragma unroll
            for (int c2 = 0; c2 < 8; ++c2)
                cpa16(stg + swz(bLOff + c2 * 16), srcB + c2 * 16);
        }
        CP_COMMIT();
    }

    float acc[4][8][4];
    #pragma unroll
    for (int a = 0; a < 4; ++a)
        #pragma unroll
        for (int b = 0; b < 8; ++b)
            #pragma unroll
            for (int q = 0; q < 4; ++q) acc[a][b][q] = 0.0f;

    for (int c = 0; c < nch; ++c) {
        CP_WAIT2();
        __syncthreads();

        if (c + 3 < nch) {
            unsigned stg = smBase + ((c + 3) & 3) * STAGE_BYTES;
            if (tid < 128) {
                const char* srcA = (const char*)(growA + (long)(c + 3) * 64);
                #pragma unroll
                for (int c2 = 0; c2 < 8; ++c2)
                    cpa16(stg + swz(aLOff + c2 * 16), srcA + c2 * 16);
            }
            const char* srcB = (const char*)(growB + (long)(c + 3) * 64);
            #pragma unroll
            for (int c2 = 0; c2 < 8; ++c2)
                cpa16(stg + swz(bLOff + c2 * 16), srcB + c2 * 16);
        }
        CP_COMMIT();

        const unsigned aB = smBase + (c & 3) * STAGE_BYTES;
        const unsigned bB = aB + 16384;

        #pragma unroll
        for (int ks = 0; ks < 2; ++ks) {
            const int caH = ks * 2, caL = 4 + ks * 2;
            unsigned aH[4][4], aL[4][4];
            #pragma unroll
            for (int mt = 0; mt < 4; ++mt) {
                unsigned r = wm * 64 + mt * 16 + (lane & 15);
                unsigned ca = (unsigned)(lane >> 4);
                LDSM_X4(aH[mt], aB + swz(r * 128 + (caH + ca) * 16));
                LDSM_X4(aL[mt], aB + swz(r * 128 + (caL + ca) * 16));
            }
            #pragma unroll
            for (int p = 0; p < 4; ++p) {
                unsigned bH[4];
                unsigned r = wn * 64 + p * 16 + (lane & 7) + ((lane >> 4) << 3);
                unsigned ca = (unsigned)((lane >> 3) & 1);
                LDSM_X4(bH, bB + swz(r * 128 + (caH + ca) * 16));
                #pragma unroll
                for (int mt = 0; mt < 4; ++mt)
                    #pragma unroll
                    for (int s2 = 0; s2 < 2; ++s2) {
                        float* cc = acc[mt][p * 2 + s2];
                        MMA_F16(cc, aH[mt], bH + 2 * s2);  // hi*hi
                        MMA_F16(cc, aL[mt], bH + 2 * s2);  // lo*hi
                    }
            }
        }
    }

    // ---- epilogue ----
    const float* bias = (EPI == 1 || EPI == 3) ? (biasBase + (long)bIdx * biasZ) : nullptr;

    #pragma unroll
    for (int mt = 0; mt < 4; ++mt) {
        #pragma unroll
        for (int half = 0; half < 2; ++half) {
            const int r = crow + wm * 64 + mt * 16 + gid + 8 * half;
            if (EPI <= 1) {
                unsigned short* dst = (unsigned short*)Cout + (long)z * Cz + (long)r * 2 * Nn;
                #pragma unroll
                for (int nj = 0; nj < 8; ++nj) {
                    const int cg = ccol + wn * 64 + nj * 8 + 2 * tig;
                    float v0 = acc[mt][nj][2 * half];
                    float v1 = acc[mt][nj][2 * half + 1];
                    if (EPI == 1) {
                        v0 = gelu(v0 + bias[cg]);
                        v1 = gelu(v1 + bias[cg + 1]);
                    }
                    __half h0, l0, h1, l1;
                    split_h(v0, h0, l0); split_h(v1, h1, l1);
                    __half2 ph; ph.x = h0; ph.y = h1;
                    __half2 pl; pl.x = l0; pl.y = l1;
                    long gb = (long)(cg >> 5) * 64 + (cg & 31);
                    *(__half2*)(dst + gb)      = ph;
                    *(__half2*)(dst + gb + 32) = pl;
                }
            } else {
                float* dst = (float*)Cout + (long)z * Cz + (long)r * ldc;
                #pragma unroll
                for (int nj = 0; nj < 8; ++nj) {
                    const int cg = ccol + wn * 64 + nj * 8 + 2 * tig;
                    float v0 = acc[mt][nj][2 * half];
                    float v1 = acc[mt][nj][2 * half + 1];
                    if (EPI == 3) { v0 += bias[cg]; v1 += bias[cg + 1]; }
                    float2 p; p.x = v0; p.y = v1;
                    *(float2*)(dst + cg) = p;
                }
            }
        }
    }
}

} // namespace

extern "C" void kernel_launch(void* const* d_in, const int* in_sizes, int n_in,
                              void* d_out, int out_size)
{
    const float* x    = (const float*)d_in[0];
    const float* dm   = (const float*)d_in[1];
    const float* comb = (const float*)d_in[2];
    const float* w1   = (const float*)d_in[3];
    const float* b1   = (const float*)d_in[4];
    const float* w2   = (const float*)d_in[5];
    const float* b2   = (const float*)d_in[6];
    float* out = (float*)d_out;

    unsigned short *A1p, *B1p, *B2p, *B3p, *A2p, *A3p, *B4p, *A4p;
    float* yscr;
    cudaGetSymbolAddress((void**)&A1p, g_A1p);
    cudaGetSymbolAddress((void**)&B1p, g_B1p);
    cudaGetSymbolAddress((void**)&B2p, g_B2p);
    cudaGetSymbolAddress((void**)&B3p, g_B3p);
    cudaGetSymbolAddress((void**)&A2p, g_A2p);
    cudaGetSymbolAddress((void**)&A3p, g_A3p);
    cudaGetSymbolAddress((void**)&B4p, g_B4p);
    cudaGetSymbolAddress((void**)&A4p, g_A4p);
    cudaGetSymbolAddress((void**)&yscr, g_y);

    cudaFuncSetAttribute(bgemm<0>, cudaFuncAttributeMaxDynamicSharedMemorySize, SMEM_DYN);
    cudaFuncSetAttribute(bgemm<1>, cudaFuncAttributeMaxDynamicSharedMemorySize, SMEM_DYN);
    cudaFuncSetAttribute(bgemm<2>, cudaFuncAttributeMaxDynamicSharedMemorySize, SMEM_DYN);
    cudaFuncSetAttribute(bgemm<3>, cudaFuncAttributeMaxDynamicSharedMemorySize, SMEM_DYN);

    dim3 pblk(32, 8);
    // #1 dm^T -> A1p : per (b,e), out [C][T]
    pack_t<<<dim3(C/32, T/32, Bsz*E), pblk>>>(dm, A1p, T, E*C,
        (long)T*E*C, (long)C, E, (long)C*2*T);
    // #2 x^T -> B1p : per b, out [D][T]
    pack_t<<<dim3(D/32, T/32, Bsz), pblk>>>(x, B1p, T, D,
        (long)T*D, 0L, 1, (long)D*2*T);
    // #3 S1: xd = dm^T * x  (M=C, N=D, K=T) packed -> A2p   [profiled slot]
    bgemm<0><<<dim3(D/256, C/128, Bsz*E), 256, SMEM_DYN>>>(
        A1p, B1p, A2p, nullptr, T, D, D,
        (long)C*2*T, (long)D*2*T, (long)C*2*D, 0L, 4);
    // #4 w1^T -> B2p : per e, out [HE][D]
    pack_t<<<dim3(HE/32, D/32, E), pblk>>>(w1, B2p, D, HE,
        (long)D*HE, 0L, 1, (long)HE*2*D);
    // #5 w2^T -> B3p : per e, out [O][HE]
    pack_t<<<dim3(O/32, HE/32, E), pblk>>>(w2, B3p, HE, O,
        (long)HE*O, 0L, 1, (long)O*2*HE);
    // #6 comb -> A4p : flat [B*T][E*C]
    {
        long n4 = (long)Bsz * T * E * C / 4;
        pack_nt<<<(unsigned)(n4 / 256), 256>>>(comb, A4p, n4, E*C);
    }
    // #7 S2: h = gelu(xd*w1 + b1)  (K=D) packed -> A3p
    bgemm<1><<<dim3(HE/256, C/128, Bsz*E), 256, SMEM_DYN>>>(
        A2p, B2p, A3p, b1, D, HE, HE,
        (long)C*2*D, (long)HE*2*D, (long)C*2*HE, (long)HE, 1);
    // #8 S3: y = h*w2  (K=HE) fp32 -> yscr
    bgemm<2><<<dim3(O/256, C/128, Bsz*E), 256, SMEM_DYN>>>(
        A3p, B3p, yscr, nullptr, HE, O, O,
        (long)C*2*HE, (long)O*2*HE, (long)C*O, 0L, 1);
    // #9 y^T -> B4p : per b, out [O][E*C]
    pack_t<<<dim3(O/32, (E*C)/32, Bsz), pblk>>>(yscr, B4p, E*C, O,
        (long)E*C*O, 0L, 1, (long)O*2*E*C);
    // #10 S4: out = comb * y^T + b2  (M=T, N=O, K=E*C) fp32 out
    bgemm<3><<<dim3(O/256, T/128, Bsz), 256, SMEM_DYN>>>(
        A4p, B4p, out, b2, E*C, O, O,
        (long)T*2*E*C, (long)O*2*E*C, (long)T*O, 0L, 1);
}

// round 7
// speedup vs baseline: 2.5940x; 1.1294x over previous
#include <cuda_runtime.h>
#include <cuda_fp16.h>
#include <math.h>

namespace {

constexpr int Bsz = 4, T = 2048, D = 512, E = 4, C = 1024, HE = 512, O = 512;
constexpr int STG = 4;
constexpr int STAGE_BYTES = 24576;               // 16KB A (hi/lo) + 8KB B (hi only)
constexpr int SMEM_DYN = STG * STAGE_BYTES + 1024;

// A operands: packed hi/lo fp16, row = [K/32 groups][32 hi | 32 lo]
// B operands: hi-only fp16, row = K contiguous halfs
__device__ __align__(256) unsigned short g_A1p[(size_t)Bsz*E*C*2*T];    // dm^T  [be][C][2T]
__device__ __align__(256) unsigned short g_B1p[(size_t)Bsz*D*T];        // x^T   [b][D][T] hi
__device__ __align__(256) unsigned short g_B2p[(size_t)E*HE*D];         // w1^T  [e][HE][D] hi
__device__ __align__(256) unsigned short g_B3p[(size_t)E*O*HE];         // w2^T  [e][O][HE] hi
__device__ __align__(256) unsigned short g_A2p[(size_t)Bsz*E*C*2*D];    // xd    [be][C][2D]
__device__ __align__(256) unsigned short g_A3p[(size_t)Bsz*E*C*2*HE];   // h     [be][C][2HE]
__device__ __align__(256) float          g_y  [(size_t)Bsz*E*C*O];      // fp32 y
__device__ __align__(256) unsigned short g_B4p[(size_t)Bsz*O*E*C];      // y^T   [b][O][EC] hi
__device__ __align__(256) unsigned short g_A4p[(size_t)Bsz*T*2*E*C];    // comb  [b*T][2EC]

__device__ __forceinline__ unsigned smem_u32(const void* p) {
    unsigned a;
    asm("{ .reg .u64 t; cvta.to.shared.u64 t, %1; cvt.u32.u64 %0, t; }" : "=r"(a) : "l"(p));
    return a;
}
__device__ __forceinline__ unsigned swz(unsigned o) { return o ^ ((o >> 3) & 0x70); }

__device__ __forceinline__ void split_h(float v, __half& h, __half& l) {
    h = __float2half_rn(v);
    l = __float2half_rn(v - __half2float(h));
}
__device__ __forceinline__ float gelu(float v) {
    return 0.5f * v * (1.0f + erff(v * 0.70710678118654752f));
}
__device__ __forceinline__ void cpa16(unsigned d, const void* s) {
    asm volatile("cp.async.cg.shared.global [%0], [%1], 16;" :: "r"(d), "l"(s) : "memory");
}
#define CP_COMMIT() asm volatile("cp.async.commit_group;" ::: "memory")
#define CP_WAIT2()  asm volatile("cp.async.wait_group 2;" ::: "memory")

#define LDSM_X4(R, addr) \
    asm volatile("ldmatrix.sync.aligned.m8n8.x4.shared.b16 {%0,%1,%2,%3}, [%4];" \
        : "=r"((R)[0]), "=r"((R)[1]), "=r"((R)[2]), "=r"((R)[3]) : "r"(addr))

#define MMA_F16(Cc, Aa, Bb) \
    asm volatile("mma.sync.aligned.m16n8k16.row.col.f32.f16.f16.f32 " \
        "{%0,%1,%2,%3}, {%4,%5,%6,%7}, {%8,%9}, {%0,%1,%2,%3};" \
        : "+f"((Cc)[0]), "+f"((Cc)[1]), "+f"((Cc)[2]), "+f"((Cc)[3]) \
        : "r"((Aa)[0]), "r"((Aa)[1]), "r"((Aa)[2]), "r"((Aa)[3]), \
          "r"((Bb)[0]), "r"((Bb)[1]))

// ---------------- pack kernels ----------------
// full hi/lo, no transpose: in [R, Kdim] fp32 -> [R][K/32][32hi|32lo]
__global__ void pack_nt(const float* __restrict__ in, unsigned short* __restrict__ outRaw,
                        long n4, int Kdim) {
    long i = (long)blockIdx.x * blockDim.x + threadIdx.x;
    if (i >= n4) return;
    __half* out = (__half*)outRaw;
    long e = i * 4;
    long r = e / Kdim; int k = (int)(e % Kdim);
    float4 v = *(const float4*)(in + e);
    int g = k >> 5, j = k & 31;
    long base = (r * (long)(Kdim >> 5) + g) * 64;
    __half h0,h1,h2,h3,l0,l1,l2,l3;
    split_h(v.x,h0,l0); split_h(v.y,h1,l1); split_h(v.z,h2,l2); split_h(v.w,h3,l3);
    __half2 p;
    p.x=h0; p.y=h1; *(__half2*)(out + base + j)          = p;
    p.x=h2; p.y=h3; *(__half2*)(out + base + j + 2)      = p;
    p.x=l0; p.y=l1; *(__half2*)(out + base + 32 + j)     = p;
    p.x=l2; p.y=l3; *(__half2*)(out + base + 32 + j + 2) = p;
}

// full hi/lo transpose: out[m] row from in[k][m]
__global__ void pack_t(const float* __restrict__ inBase, unsigned short* __restrict__ outRaw,
                       int Kdim, int rs, long inZdiv, long inZmod, int zdiv, long outZ) {
    int z = blockIdx.z;
    const float* in = inBase + (long)(z / zdiv) * inZdiv + (long)(z % zdiv) * inZmod;
    __half* out = (__half*)outRaw + (long)z * outZ;
    __shared__ float t[32][33];
    int m0 = blockIdx.x * 32, k0 = blockIdx.y * 32;
    int tx = threadIdx.x, ty = threadIdx.y;  // 32 x 8
    #pragma unroll
    for (int i = 0; i < 4; ++i)
        t[ty + 8*i][tx] = in[(long)(k0 + ty + 8*i) * rs + m0 + tx];
    __syncthreads();
    #pragma unroll
    for (int i = 0; i < 4; ++i) {
        int r = ty + 8*i;
        long base = ((long)(m0 + r) * (Kdim >> 5) + (k0 >> 5)) * 64;
        int w = tx;
        int j = (w < 16) ? 2*w : 2*(w - 16);
        float v0 = t[j][r], v1 = t[j+1][r];
        __half a0,b0,a1,b1;
        split_h(v0,a0,b0); split_h(v1,a1,b1);
        __half2 p;
        if (w < 16) { p.x=a0; p.y=a1; *(__half2*)(out + base + 2*w) = p; }
        else        { p.x=b0; p.y=b1; *(__half2*)(out + base + 32 + 2*(w-16)) = p; }
    }
}

// hi-only transpose: out rows contiguous K halfs
__global__ void pack_t_hi(const float* __restrict__ inBase, unsigned short* __restrict__ outRaw,
                          int Kdim, int rs, long inZdiv, long inZmod, int zdiv, long outZ) {
    int z = blockIdx.z;
    const float* in = inBase + (long)(z / zdiv) * inZdiv + (long)(z % zdiv) * inZmod;
    __half* out = (__half*)outRaw + (long)z * outZ;
    __shared__ float t[32][33];
    int m0 = blockIdx.x * 32, k0 = blockIdx.y * 32;
    int tx = threadIdx.x, ty = threadIdx.y;  // 32 x 8
    #pragma unroll
    for (int i = 0; i < 4; ++i)
        t[ty + 8*i][tx] = in[(long)(k0 + ty + 8*i) * rs + m0 + tx];
    __syncthreads();
    #pragma unroll
    for (int i = 0; i < 4; ++i) {
        int r = ty + 8*i;
        out[(long)(m0 + r) * Kdim + k0 + tx] = __float2half_rn(t[tx][r]);
    }
}

// ------- mma.sync fp16 2-term GEMM, CTA 128x128, warp 32x64, 2 CTA/SM -------
// C = (A_hi + A_lo) * B_hi  (error = A*B_lo ~ 2^-12 relative)
// EPI: 0 = packed out; 1 = packed out + bias + GELU; 2 = fp32 out; 3 = fp32 out + bias
template <int EPI>
__global__ __launch_bounds__(256, 2)
void bgemm(const unsigned short* __restrict__ Ap,
           const unsigned short* __restrict__ Bp,
           void* __restrict__ Cout,
           const float* __restrict__ biasBase,
           int K, int Nn, int ldc,
           long Az, long Bz, long Cz, long biasZ, int bDiv)
{
    extern __shared__ char dynsm[];
    const unsigned smBase = (smem_u32(dynsm) + 1023u) & ~1023u;

    const int tid  = threadIdx.x;
    const int z    = blockIdx.z;
    const int bIdx = (z / bDiv) % E;
    const int crow = blockIdx.y * 128;
    const int ccol = blockIdx.x * 128;

    const int lane = tid & 31;
    const int warp = tid >> 5;
    const int wm   = warp & 3;   // 0..3 -> 32-row block
    const int wn   = warp >> 2;  // 0..1 -> 64-col block
    const int gid  = lane >> 2, tig = lane & 3;

    // loaders: all 256 threads; A row = tid&127 (4x16B each), B row = tid&127 (2x16B each)
    const int lrow = tid & 127;
    const unsigned short* growA = Ap + (long)z * Az + (long)(crow + lrow) * (2L * K);
    const unsigned short* growB = Bp + (long)bIdx * Bz + (long)(ccol + lrow) * (long)K;
    const int aU0 = (tid >> 7) * 4;      // 0 or 4
    const int bU0 = (tid >> 7) * 2;      // 0 or 2
    const unsigned bSw = (unsigned)((lrow >> 1) & 3);

    unsigned aOff[4], bOff[2];
    #pragma unroll
    for (int u = 0; u < 4; ++u)
        aOff[u] = swz((unsigned)(lrow * 128 + (aU0 + u) * 16));
    #pragma unroll
    for (int u = 0; u < 2; ++u)
        bOff[u] = 16384u + (unsigned)(lrow * 64) + ((((unsigned)(bU0 + u)) ^ bSw) << 4);

    const int nch = K / 32;

    #pragma unroll
    for (int s = 0; s < 3; ++s) {
        unsigned stg = smBase + s * STAGE_BYTES;
        const char* srcA = (const char*)(growA + (long)s * 64);
        #pragma unroll
        for (int u = 0; u < 4; ++u) cpa16(stg + aOff[u], srcA + (aU0 + u) * 16);
        const char* srcB = (const char*)(growB + (long)s * 32);
        #pragma unroll
        for (int u = 0; u < 2; ++u) cpa16(stg + bOff[u], srcB + (bU0 + u) * 16);
        CP_COMMIT();
    }

    float acc[2][8][4];
    #pragma unroll
    for (int a = 0; a < 2; ++a)
        #pragma unroll
        for (int b = 0; b < 8; ++b)
            #pragma unroll
            for (int q = 0; q < 4; ++q) acc[a][b][q] = 0.0f;

    for (int c = 0; c < nch; ++c) {
        CP_WAIT2();
        __syncthreads();

        if (c + 3 < nch) {
            unsigned stg = smBase + ((c + 3) & 3) * STAGE_BYTES;
            const char* srcA = (const char*)(growA + (long)(c + 3) * 64);
            #pragma unroll
            for (int u = 0; u < 4; ++u) cpa16(stg + aOff[u], srcA + (aU0 + u) * 16);
            const char* srcB = (const char*)(growB + (long)(c + 3) * 32);
            #pragma unroll
            for (int u = 0; u < 2; ++u) cpa16(stg + bOff[u], srcB + (bU0 + u) * 16);
        }
        CP_COMMIT();

        const unsigned aB = smBase + (c & 3) * STAGE_BYTES;
        const unsigned bB = aB + 16384;

        #pragma unroll
        for (int ks = 0; ks < 2; ++ks) {
            const int caH = ks * 2, caL = 4 + ks * 2;
            unsigned aH[2][4], aL[2][4];
            #pragma unroll
            for (int mt = 0; mt < 2; ++mt) {
                unsigned r = wm * 32 + mt * 16 + (lane & 15);
                unsigned ca = (unsigned)(lane >> 4);
                LDSM_X4(aH[mt], aB + swz(r * 128 + (caH + ca) * 16));
                LDSM_X4(aL[mt], aB + swz(r * 128 + (caL + ca) * 16));
            }
            #pragma unroll
            for (int p = 0; p < 4; ++p) {
                unsigned bH[4];
                unsigned r = wn * 64 + p * 16 + (lane & 7) + ((lane >> 4) << 3);
                unsigned cu = (unsigned)(caH + ((lane >> 3) & 1));
                LDSM_X4(bH, bB + r * 64 + ((cu ^ ((r >> 1) & 3)) << 4));
                #pragma unroll
                for (int mt = 0; mt < 2; ++mt)
                    #pragma unroll
                    for (int s2 = 0; s2 < 2; ++s2) {
                        float* cc = acc[mt][p * 2 + s2];
                        MMA_F16(cc, aH[mt], bH + 2 * s2);  // hi*hi
                        MMA_F16(cc, aL[mt], bH + 2 * s2);  // lo*hi
                    }
            }
        }
    }

    // ---- epilogue ----
    const float* bias = (EPI == 1 || EPI == 3) ? (biasBase + (long)bIdx * biasZ) : nullptr;

    #pragma unroll
    for (int mt = 0; mt < 2; ++mt) {
        #pragma unroll
        for (int half = 0; half < 2; ++half) {
            const int r = crow + wm * 32 + mt * 16 + gid + 8 * half;
            if (EPI <= 1) {
                unsigned short* dst = (unsigned short*)Cout + (long)z * Cz + (long)r * 2 * Nn;
                #pragma unroll
                for (int nj = 0; nj < 8; ++nj) {
                    const int cg = ccol + wn * 64 + nj * 8 + 2 * tig;
                    float v0 = acc[mt][nj][2 * half];
                    float v1 = acc[mt][nj][2 * half + 1];
                    if (EPI == 1) {
                        v0 = gelu(v0 + bias[cg]);
                        v1 = gelu(v1 + bias[cg + 1]);
                    }
                    __half h0, l0, h1, l1;
                    split_h(v0, h0, l0); split_h(v1, h1, l1);
                    __half2 ph; ph.x = h0; ph.y = h1;
                    __half2 pl; pl.x = l0; pl.y = l1;
                    long gb = (long)(cg >> 5) * 64 + (cg & 31);
                    *(__half2*)(dst + gb)      = ph;
                    *(__half2*)(dst + gb + 32) = pl;
                }
            } else {
                float* dst = (float*)Cout + (long)z * Cz + (long)r * ldc;
                #pragma unroll
                for (int nj = 0; nj < 8; ++nj) {
                    const int cg = ccol + wn * 64 + nj * 8 + 2 * tig;
                    float v0 = acc[mt][nj][2 * half];
                    float v1 = acc[mt][nj][2 * half + 1];
                    if (EPI == 3) { v0 += bias[cg]; v1 += bias[cg + 1]; }
                    float2 p; p.x = v0; p.y = v1;
                    *(float2*)(dst + cg) = p;
                }
            }
        }
    }
}

} // namespace

extern "C" void kernel_launch(void* const* d_in, const int* in_sizes, int n_in,
                              void* d_out, int out_size)
{
    const float* x    = (const float*)d_in[0];
    const float* dm   = (const float*)d_in[1];
    const float* comb = (const float*)d_in[2];
    const float* w1   = (const float*)d_in[3];
    const float* b1   = (const float*)d_in[4];
    const float* w2   = (const float*)d_in[5];
    const float* b2   = (const float*)d_in[6];
    float* out = (float*)d_out;

    unsigned short *A1p, *B1p, *B2p, *B3p, *A2p, *A3p, *B4p, *A4p;
    float* yscr;
    cudaGetSymbolAddress((void**)&A1p, g_A1p);
    cudaGetSymbolAddress((void**)&B1p, g_B1p);
    cudaGetSymbolAddress((void**)&B2p, g_B2p);
    cudaGetSymbolAddress((void**)&B3p, g_B3p);
    cudaGetSymbolAddress((void**)&A2p, g_A2p);
    cudaGetSymbolAddress((void**)&A3p, g_A3p);
    cudaGetSymbolAddress((void**)&B4p, g_B4p);
    cudaGetSymbolAddress((void**)&A4p, g_A4p);
    cudaGetSymbolAddress((void**)&yscr, g_y);

    cudaFuncSetAttribute(bgemm<0>, cudaFuncAttributeMaxDynamicSharedMemorySize, SMEM_DYN);
    cudaFuncSetAttribute(bgemm<1>, cudaFuncAttributeMaxDynamicSharedMemorySize, SMEM_DYN);
    cudaFuncSetAttribute(bgemm<2>, cudaFuncAttributeMaxDynamicSharedMemorySize, SMEM_DYN);
    cudaFuncSetAttribute(bgemm<3>, cudaFuncAttributeMaxDynamicSharedMemorySize, SMEM_DYN);

    dim3 pblk(32, 8);
    // #1 dm^T -> A1p (full hi/lo): per (b,e), out [C][2T]
    pack_t<<<dim3(C/32, T/32, Bsz*E), pblk>>>(dm, A1p, T, E*C,
        (long)T*E*C, (long)C, E, (long)C*2*T);
    // #2 x^T -> B1p (hi only): per b, out [D][T]
    pack_t_hi<<<dim3(D/32, T/32, Bsz), pblk>>>(x, B1p, T, D,
        (long)T*D, 0L, 1, (long)D*T);
    // #3 w1^T -> B2p (hi only): per e, out [HE][D]
    pack_t_hi<<<dim3(HE/32, D/32, E), pblk>>>(w1, B2p, D, HE,
        (long)D*HE, 0L, 1, (long)HE*D);
    // #4 S1: xd = dm^T * x  (M=C, N=D, K=T) packed -> A2p   [profiled slot]
    bgemm<0><<<dim3(D/128, C/128, Bsz*E), 256, SMEM_DYN>>>(
        A1p, B1p, A2p, nullptr, T, D, D,
        (long)C*2*T, (long)D*T, (long)C*2*D, 0L, 4);
    // #5 w2^T -> B3p (hi only): per e, out [O][HE]
    pack_t_hi<<<dim3(O/32, HE/32, E), pblk>>>(w2, B3p, HE, O,
        (long)HE*O, 0L, 1, (long)O*HE);
    // #6 comb -> A4p (full hi/lo): flat [B*T][2EC]
    {
        long n4 = (long)Bsz * T * E * C / 4;
        pack_nt<<<(unsigned)(n4 / 256), 256>>>(comb, A4p, n4, E*C);
    }
    // #7 S2: h = gelu(xd*w1 + b1)  (K=D) packed -> A3p
    bgemm<1><<<dim3(HE/128, C/128, Bsz*E), 256, SMEM_DYN>>>(
        A2p, B2p, A3p, b1, D, HE, HE,
        (long)C*2*D, (long)HE*D, (long)C*2*HE, (long)HE, 1);
    // #8 S3: y = h*w2  (K=HE) fp32 -> yscr
    bgemm<2><<<dim3(O/128, C/128, Bsz*E), 256, SMEM_DYN>>>(
        A3p, B3p, yscr, nullptr, HE, O, O,
        (long)C*2*HE, (long)O*HE, (long)C*O, 0L, 1);
    // #9 y^T -> B4p (hi only): per b, out [O][EC]
    pack_t_hi<<<dim3(O/32, (E*C)/32, Bsz), pblk>>>(yscr, B4p, E*C, O,
        (long)E*C*O, 0L, 1, (long)O*E*C);
    // #10 S4: out = comb * y^T + b2  (M=T, N=O, K=EC) fp32 out
    bgemm<3><<<dim3(O/128, T/128, Bsz), 256, SMEM_DYN>>>(
        A4p, B4p, out, b2, E*C, O, O,
        (long)T*2*E*C, (long)O*E*C, (long)T*O, 0L, 1);
}

// round 8
// speedup vs baseline: 4.2301x; 1.6307x over previous
#include <cuda_runtime.h>
#include <cuda_fp16.h>
#include <math.h>

namespace {

constexpr int Bsz = 4, T = 2048, D = 512, E = 4, C = 1024, HE = 512, O = 512;
constexpr int STAGE_BYTES = 24576;               // 16KB A (hi/lo) + 8KB B (hi only)
constexpr int SMEM_DYN = 4 * STAGE_BYTES + 1024;

// A operands: tile-contiguous packed hi/lo fp16, pre-swizzled:
//   [mtile][chunk][row 0..127][64 halfs = 32hi|32lo, 16B-unit u stored at u^(row&7)]
// B operands: tile-contiguous hi-only fp16, pre-swizzled:
//   [ntile][chunk][row 0..127][32 halfs, 16B-unit u stored at u^((row>>1)&3)]
__device__ __align__(256) unsigned short g_A1p[(size_t)Bsz*E*C*2*T];    // dm^T  [be]
__device__ __align__(256) unsigned short g_B1p[(size_t)Bsz*D*T];        // x^T   [b]
__device__ __align__(256) unsigned short g_B2p[(size_t)E*HE*D];         // w1^T  [e]
__device__ __align__(256) unsigned short g_B3p[(size_t)E*O*HE];         // w2^T  [e]
__device__ __align__(256) unsigned short g_A2p[(size_t)Bsz*E*C*2*D];    // xd    [be]
__device__ __align__(256) unsigned short g_A3p[(size_t)Bsz*E*C*2*HE];   // h     [be]
__device__ __align__(256) float          g_y  [(size_t)Bsz*E*C*O];      // fp32 y
__device__ __align__(256) unsigned short g_B4p[(size_t)Bsz*O*E*C];      // y^T   [b]
__device__ __align__(256) unsigned short g_A4p[(size_t)Bsz*T*2*E*C];    // comb  [b]

__device__ __forceinline__ unsigned smem_u32(const void* p) {
    unsigned a;
    asm("{ .reg .u64 t; cvta.to.shared.u64 t, %1; cvt.u32.u64 %0, t; }" : "=r"(a) : "l"(p));
    return a;
}
__device__ __forceinline__ void split_h(float v, __half& h, __half& l) {
    h = __float2half_rn(v);
    l = __float2half_rn(v - __half2float(h));
}
__device__ __forceinline__ float gelu(float v) {
    return 0.5f * v * (1.0f + erff(v * 0.70710678118654752f));
}

__device__ __forceinline__ void mbar_init(unsigned a, unsigned cnt) {
    asm volatile("mbarrier.init.shared.b64 [%0], %1;" :: "r"(a), "r"(cnt) : "memory");
}
__device__ __forceinline__ void mbar_arrive(unsigned a) {
    asm volatile("mbarrier.arrive.shared.b64 _, [%0];" :: "r"(a) : "memory");
}
__device__ __forceinline__ void mbar_expect_tx(unsigned a, unsigned bytes) {
    asm volatile("mbarrier.arrive.expect_tx.shared.b64 _, [%0], %1;"
                 :: "r"(a), "r"(bytes) : "memory");
}
__device__ __forceinline__ void mbar_wait(unsigned a, unsigned par) {
    asm volatile("{\n\t.reg .pred P;\n"
                 "WL%=:\n\t"
                 "mbarrier.try_wait.parity.acquire.cta.shared::cta.b64 P, [%0], %1, 0x989680;\n\t"
                 "@P bra.uni WD%=;\n\t"
                 "bra.uni WL%=;\n"
                 "WD%=:\n\t}" :: "r"(a), "r"(par) : "memory");
}
__device__ __forceinline__ void bulk_g2s(unsigned dst, const void* src,
                                         unsigned bytes, unsigned mbar) {
    asm volatile("cp.async.bulk.shared::cluster.global.mbarrier::complete_tx::bytes "
                 "[%0], [%1], %2, [%3];"
                 :: "r"(dst), "l"(src), "r"(bytes), "r"(mbar) : "memory");
}

#define LDSM_X4(R, addr) \
    asm volatile("ldmatrix.sync.aligned.m8n8.x4.shared.b16 {%0,%1,%2,%3}, [%4];" \
        : "=r"((R)[0]), "=r"((R)[1]), "=r"((R)[2]), "=r"((R)[3]) : "r"(addr))

#define MMA_F16(Cc, Aa, Bb) \
    asm volatile("mma.sync.aligned.m16n8k16.row.col.f32.f16.f16.f32 " \
        "{%0,%1,%2,%3}, {%4,%5,%6,%7}, {%8,%9}, {%0,%1,%2,%3};" \
        : "+f"((Cc)[0]), "+f"((Cc)[1]), "+f"((Cc)[2]), "+f"((Cc)[3]) \
        : "r"((Aa)[0]), "r"((Aa)[1]), "r"((Aa)[2]), "r"((Aa)[3]), \
          "r"((Bb)[0]), "r"((Bb)[1]))

// ---------------- pack kernels (tile-contiguous + swizzled) ----------------
// A full hi/lo, no transpose: in [R, Kdim] fp32
__global__ void pack_nt(const float* __restrict__ in, unsigned short* __restrict__ outRaw,
                        long n4, int Kdim) {
    long i = (long)blockIdx.x * blockDim.x + threadIdx.x;
    if (i >= n4) return;
    __half* out = (__half*)outRaw;
    long e = i * 4;
    long r = e / Kdim; int k = (int)(e % Kdim);
    float4 v = *(const float4*)(in + e);
    int g = k >> 5, j = k & 31;
    long tb = ((r >> 7) * (long)(Kdim >> 5) + g) * 8192 + (r & 127) * 64;
    int ru = (int)(r & 7);
    __half h0,h1,h2,h3,l0,l1,l2,l3;
    split_h(v.x,h0,l0); split_h(v.y,h1,l1); split_h(v.z,h2,l2); split_h(v.w,h3,l3);
    auto sw = [&](int jj) { int u = jj >> 3; return tb + (((u ^ ru) & 7) << 3) + (jj & 7); };
    __half2 p;
    p.x=h0; p.y=h1; *(__half2*)(out + sw(j))          = p;
    p.x=h2; p.y=h3; *(__half2*)(out + sw(j + 2))      = p;
    p.x=l0; p.y=l1; *(__half2*)(out + sw(32 + j))     = p;
    p.x=l2; p.y=l3; *(__half2*)(out + sw(32 + j + 2)) = p;
}

// A full hi/lo transpose: out[m] from in[k][m]
__global__ void pack_t(const float* __restrict__ inBase, unsigned short* __restrict__ outRaw,
                       int Kdim, int rs, long inZdiv, long inZmod, int zdiv, long outZ) {
    int z = blockIdx.z;
    const float* in = inBase + (long)(z / zdiv) * inZdiv + (long)(z % zdiv) * inZmod;
    __half* out = (__half*)outRaw + (long)z * outZ;
    __shared__ float t[32][33];
    int m0 = blockIdx.x * 32, k0 = blockIdx.y * 32;
    int tx = threadIdx.x, ty = threadIdx.y;  // 32 x 8
    #pragma unroll
    for (int i = 0; i < 4; ++i)
        t[ty + 8*i][tx] = in[(long)(k0 + ty + 8*i) * rs + m0 + tx];
    __syncthreads();
    int g = k0 >> 5;
    #pragma unroll
    for (int i = 0; i < 4; ++i) {
        int r = ty + 8*i;
        int m = m0 + r;
        long tb = ((long)(m >> 7) * (Kdim >> 5) + g) * 8192 + (m & 127) * 64;
        int ru = m & 7;
        int w = tx;
        int jsrc = (w < 16) ? 2*w : 2*(w - 16);
        float v0 = t[jsrc][r], v1 = t[jsrc+1][r];
        __half a0,b0,a1,b1;
        split_h(v0,a0,b0); split_h(v1,a1,b1);
        int j = (w < 16) ? 2*w : 32 + 2*(w - 16);
        int u = j >> 3;
        long idx = tb + (((u ^ ru) & 7) << 3) + (j & 7);
        __half2 p;
        if (w < 16) { p.x=a0; p.y=a1; }
        else        { p.x=b0; p.y=b1; }
        *(__half2*)(out + idx) = p;
    }
}

// B hi-only transpose
__global__ void pack_t_hi(const float* __restrict__ inBase, unsigned short* __restrict__ outRaw,
                          int Kdim, int rs, long inZdiv, long inZmod, int zdiv, long outZ) {
    int z = blockIdx.z;
    const float* in = inBase + (long)(z / zdiv) * inZdiv + (long)(z % zdiv) * inZmod;
    __half* out = (__half*)outRaw + (long)z * outZ;
    __shared__ float t[32][33];
    int m0 = blockIdx.x * 32, k0 = blockIdx.y * 32;
    int tx = threadIdx.x, ty = threadIdx.y;  // 32 x 8
    #pragma unroll
    for (int i = 0; i < 4; ++i)
        t[ty + 8*i][tx] = in[(long)(k0 + ty + 8*i) * rs + m0 + tx];
    __syncthreads();
    int g = k0 >> 5;
    #pragma unroll
    for (int i = 0; i < 4; ++i) {
        int r = ty + 8*i;
        int n = m0 + r;
        int j = tx;                        // k within group (k0 is 32-aligned)
        int u = j >> 3;
        int jp = (((u ^ ((n >> 1) & 3)) & 3) << 3) | (j & 7);
        long idx = ((long)(n >> 7) * (Kdim >> 5) + g) * 4096 + (n & 127) * 32 + jp;
        out[idx] = __float2half_rn(t[tx][r]);
    }
}

// ------- mma.sync fp16 2-term GEMM, TMA-bulk fills, mbarrier ring -------
// C = (A_hi + A_lo) * B_hi
// EPI: 0 = packed out; 1 = packed out + bias + GELU; 2 = fp32 out; 3 = fp32 out + bias
template <int EPI>
__global__ __launch_bounds__(256, 2)
void bgemm(const unsigned short* __restrict__ Ap,
           const unsigned short* __restrict__ Bp,
           void* __restrict__ Cout,
           const float* __restrict__ biasBase,
           int K, int Nn, int ldc,
           long Az, long Bz, long Cz, long biasZ, int bDiv)
{
    extern __shared__ char dynsm[];
    __shared__ __align__(8) unsigned long long s_full[4], s_empty[4];
    const unsigned smBase = (smem_u32(dynsm) + 1023u) & ~1023u;

    const int tid  = threadIdx.x;
    const int z    = blockIdx.z;
    const int bIdx = (z / bDiv) % E;
    const int crow = blockIdx.y * 128;
    const int ccol = blockIdx.x * 128;

    const int lane = tid & 31;
    const int warp = tid >> 5;
    const int wm   = warp & 3;   // 0..3 -> 32-row block
    const int wn   = warp >> 2;  // 0..1 -> 64-col block
    const int gid  = lane >> 2, tig = lane & 3;
    const int nch  = K / 32;

    unsigned fullB[4], emptyB[4];
    #pragma unroll
    for (int s = 0; s < 4; ++s) {
        fullB[s]  = smem_u32(&s_full[s]);
        emptyB[s] = smem_u32(&s_empty[s]);
    }
    if (tid == 0) {
        #pragma unroll
        for (int s = 0; s < 4; ++s) { mbar_init(fullB[s], 1); mbar_init(emptyB[s], 8); }
    }
    __syncthreads();

    const char* gA = (const char*)(Ap + (long)z * Az + (long)blockIdx.y * nch * 8192);
    const char* gB = (const char*)(Bp + (long)bIdx * Bz + (long)blockIdx.x * nch * 4096);

    if (tid == 0) {
        #pragma unroll
        for (int tc = 0; tc < 3; ++tc) {
            mbar_expect_tx(fullB[tc], STAGE_BYTES);
            bulk_g2s(smBase + tc * STAGE_BYTES,         gA + (long)tc * 16384, 16384, fullB[tc]);
            bulk_g2s(smBase + tc * STAGE_BYTES + 16384, gB + (long)tc * 8192,  8192,  fullB[tc]);
        }
    }

    float acc[2][8][4];
    #pragma unroll
    for (int a = 0; a < 2; ++a)
        #pragma unroll
        for (int b = 0; b < 8; ++b)
            #pragma unroll
            for (int q = 0; q < 4; ++q) acc[a][b][q] = 0.0f;

    for (int c = 0; c < nch; ++c) {
        if (tid == 0 && c + 3 < nch) {
            const int tc = c + 3, ts = tc & 3;
            if (tc >= 4) mbar_wait(emptyB[ts], ((tc - 4) >> 2) & 1);
            mbar_expect_tx(fullB[ts], STAGE_BYTES);
            bulk_g2s(smBase + ts * STAGE_BYTES,         gA + (long)tc * 16384, 16384, fullB[ts]);
            bulk_g2s(smBase + ts * STAGE_BYTES + 16384, gB + (long)tc * 8192,  8192,  fullB[ts]);
        }
        mbar_wait(fullB[c & 3], (c >> 2) & 1);

        const unsigned aB = smBase + (c & 3) * STAGE_BYTES;
        const unsigned bB = aB + 16384;

        #pragma unroll
        for (int ks = 0; ks < 2; ++ks) {
            const int caH = ks * 2, caL = 4 + ks * 2;
            unsigned aH[2][4], aL[2][4];
            #pragma unroll
            for (int mt = 0; mt < 2; ++mt) {
                unsigned r = wm * 32 + mt * 16 + (lane & 15);
                unsigned ca = (unsigned)(lane >> 4);
                LDSM_X4(aH[mt], aB + r * 128 + ((((unsigned)caH + ca) ^ (r & 7)) << 4));
                LDSM_X4(aL[mt], aB + r * 128 + ((((unsigned)caL + ca) ^ (r & 7)) << 4));
            }
            #pragma unroll
            for (int p = 0; p < 4; ++p) {
                unsigned bH[4];
                unsigned r = wn * 64 + p * 16 + (lane & 7) + ((lane >> 4) << 3);
                unsigned cu = (unsigned)(caH + ((lane >> 3) & 1));
                LDSM_X4(bH, bB + r * 64 + ((cu ^ ((r >> 1) & 3)) << 4));
                #pragma unroll
                for (int mt = 0; mt < 2; ++mt)
                    #pragma unroll
                    for (int s2 = 0; s2 < 2; ++s2) {
                        float* cc = acc[mt][p * 2 + s2];
                        MMA_F16(cc, aH[mt], bH + 2 * s2);  // hi*hi
                        MMA_F16(cc, aL[mt], bH + 2 * s2);  // lo*hi
                    }
            }
        }
        if (lane == 0) mbar_arrive(emptyB[c & 3]);
    }

    // ---- epilogue ----
    const float* bias = (EPI == 1 || EPI == 3) ? (biasBase + (long)bIdx * biasZ) : nullptr;

    #pragma unroll
    for (int mt = 0; mt < 2; ++mt) {
        #pragma unroll
        for (int half = 0; half < 2; ++half) {
            const int r = crow + wm * 32 + mt * 16 + gid + 8 * half;
            if (EPI <= 1) {
                unsigned short* dstz = (unsigned short*)Cout + (long)z * Cz;
                long rowBase = (long)(r >> 7) * (Nn >> 5) * 8192 + (long)(r & 127) * 64;
                const int ru = r & 7;
                #pragma unroll
                for (int nj = 0; nj < 8; ++nj) {
                    const int cg = ccol + wn * 64 + nj * 8 + 2 * tig;
                    float v0 = acc[mt][nj][2 * half];
                    float v1 = acc[mt][nj][2 * half + 1];
                    if (EPI == 1) {
                        v0 = gelu(v0 + bias[cg]);
                        v1 = gelu(v1 + bias[cg + 1]);
                    }
                    __half h0, l0, h1, l1;
                    split_h(v0, h0, l0); split_h(v1, h1, l1);
                    __half2 ph; ph.x = h0; ph.y = h1;
                    __half2 pl; pl.x = l0; pl.y = l1;
                    const int g = cg >> 5, j = cg & 31;
                    long tb = rowBase + (long)g * 8192;
                    int u0 = j >> 3;
                    int jp0 = (((u0 ^ ru) & 7) << 3) | (j & 7);
                    int u1 = 4 + u0;
                    int jp1 = (((u1 ^ ru) & 7) << 3) | (j & 7);
                    *(__half2*)(dstz + tb + jp0) = ph;
                    *(__half2*)(dstz + tb + jp1) = pl;
                }
            } else {
                float* dst = (float*)Cout + (long)z * Cz + (long)r * ldc;
                #pragma unroll
                for (int nj = 0; nj < 8; ++nj) {
                    const int cg = ccol + wn * 64 + nj * 8 + 2 * tig;
                    float v0 = acc[mt][nj][2 * half];
                    float v1 = acc[mt][nj][2 * half + 1];
                    if (EPI == 3) { v0 += bias[cg]; v1 += bias[cg + 1]; }
                    float2 p; p.x = v0; p.y = v1;
                    *(float2*)(dst + cg) = p;
                }
            }
        }
    }
}

} // namespace

extern "C" void kernel_launch(void* const* d_in, const int* in_sizes, int n_in,
                              void* d_out, int out_size)
{
    const float* x    = (const float*)d_in[0];
    const float* dm   = (const float*)d_in[1];
    const float* comb = (const float*)d_in[2];
    const float* w1   = (const float*)d_in[3];
    const float* b1   = (const float*)d_in[4];
    const float* w2   = (const float*)d_in[5];
    const float* b2   = (const float*)d_in[6];
    float* out = (float*)d_out;

    unsigned short *A1p, *B1p, *B2p, *B3p, *A2p, *A3p, *B4p, *A4p;
    float* yscr;
    cudaGetSymbolAddress((void**)&A1p, g_A1p);
    cudaGetSymbolAddress((void**)&B1p, g_B1p);
    cudaGetSymbolAddress((void**)&B2p, g_B2p);
    cudaGetSymbolAddress((void**)&B3p, g_B3p);
    cudaGetSymbolAddress((void**)&A2p, g_A2p);
    cudaGetSymbolAddress((void**)&A3p, g_A3p);
    cudaGetSymbolAddress((void**)&B4p, g_B4p);
    cudaGetSymbolAddress((void**)&A4p, g_A4p);
    cudaGetSymbolAddress((void**)&yscr, g_y);

    cudaFuncSetAttribute(bgemm<0>, cudaFuncAttributeMaxDynamicSharedMemorySize, SMEM_DYN);
    cudaFuncSetAttribute(bgemm<1>, cudaFuncAttributeMaxDynamicSharedMemorySize, SMEM_DYN);
    cudaFuncSetAttribute(bgemm<2>, cudaFuncAttributeMaxDynamicSharedMemorySize, SMEM_DYN);
    cudaFuncSetAttribute(bgemm<3>, cudaFuncAttributeMaxDynamicSharedMemorySize, SMEM_DYN);

    dim3 pblk(32, 8);
    // #1 dm^T -> A1p (full hi/lo): per (b,e)
    pack_t<<<dim3(C/32, T/32, Bsz*E), pblk>>>(dm, A1p, T, E*C,
        (long)T*E*C, (long)C, E, (long)C*2*T);
    // #2 x^T -> B1p (hi only): per b
    pack_t_hi<<<dim3(D/32, T/32, Bsz), pblk>>>(x, B1p, T, D,
        (long)T*D, 0L, 1, (long)D*T);
    // #3 w1^T -> B2p (hi only): per e
    pack_t_hi<<<dim3(HE/32, D/32, E), pblk>>>(w1, B2p, D, HE,
        (long)D*HE, 0L, 1, (long)HE*D);
    // #4 S1: xd = dm^T * x  (M=C, N=D, K=T) packed -> A2p   [profiled slot]
    bgemm<0><<<dim3(D/128, C/128, Bsz*E), 256, SMEM_DYN>>>(
        A1p, B1p, A2p, nullptr, T, D, D,
        (long)C*2*T, (long)D*T, (long)C*2*D, 0L, 4);
    // #5 w2^T -> B3p (hi only): per e
    pack_t_hi<<<dim3(O/32, HE/32, E), pblk>>>(w2, B3p, HE, O,
        (long)HE*O, 0L, 1, (long)O*HE);
    // #6 comb -> A4p (full hi/lo)
    {
        long n4 = (long)Bsz * T * E * C / 4;
        pack_nt<<<(unsigned)(n4 / 256), 256>>>(comb, A4p, n4, E*C);
    }
    // #7 S2: h = gelu(xd*w1 + b1)  (K=D) packed -> A3p
    bgemm<1><<<dim3(HE/128, C/128, Bsz*E), 256, SMEM_DYN>>>(
        A2p, B2p, A3p, b1, D, HE, HE,
        (long)C*2*D, (long)HE*D, (long)C*2*HE, (long)HE, 1);
    // #8 S3: y = h*w2  (K=HE) fp32 -> yscr
    bgemm<2><<<dim3(O/128, C/128, Bsz*E), 256, SMEM_DYN>>>(
        A3p, B3p, yscr, nullptr, HE, O, O,
        (long)C*2*HE, (long)O*HE, (long)C*O, 0L, 1);
    // #9 y^T -> B4p (hi only): per b
    pack_t_hi<<<dim3(O/32, (E*C)/32, Bsz), pblk>>>(yscr, B4p, E*C, O,
        (long)E*C*O, 0L, 1, (long)O*E*C);
    // #10 S4: out = comb * y^T + b2  (M=T, N=O, K=EC) fp32 out
    bgemm<3><<<dim3(O/128, T/128, Bsz), 256, SMEM_DYN>>>(
        A4p, B4p, out, b2, E*C, O, O,
        (long)T*2*E*C, (long)O*E*C, (long)T*O, 0L, 1);
}

// round 9
// speedup vs baseline: 5.8983x; 1.3944x over previous
#include <cuda_runtime.h>
#include <cuda_fp16.h>
#include <math.h>

namespace {

constexpr int Bsz = 4, T = 2048, D = 512, E = 4, C = 1024, HE = 512, O = 512;
constexpr int SMEM_DYN = 98304 + 1024;

// hi-only operands: tile blob per (128-row mtile, 32-k chunk):
//   [row 0..127][32 halfs; 16B-unit u in 0..3 stored at u^((row>>1)&3)]   (4096 halfs)
// full hi/lo operands (GEMM-epilogue-produced):
//   [row 0..127][64 halfs = 32hi|32lo; 16B-unit u in 0..7 stored at u^(row&7)] (8192 halfs)
__device__ __align__(256) unsigned short g_A1p[(size_t)Bsz*E*C*T];      // dm^T hi  [be]
__device__ __align__(256) unsigned short g_B1p[(size_t)Bsz*D*T];        // x^T  hi  [b]
__device__ __align__(256) unsigned short g_B2p[(size_t)E*HE*D];         // w1^T hi  [e]
__device__ __align__(256) unsigned short g_B3p[(size_t)E*O*HE];         // w2^T hi  [e]
__device__ __align__(256) unsigned short g_A2p[(size_t)Bsz*E*C*2*D];    // xd  full [be]
__device__ __align__(256) unsigned short g_A3p[(size_t)Bsz*E*C*2*HE];   // h   full [be]
__device__ __align__(256) float          g_y  [(size_t)Bsz*E*C*O];      // fp32 y
__device__ __align__(256) unsigned short g_B4p[(size_t)Bsz*O*E*C];      // y^T  hi  [b]
__device__ __align__(256) unsigned short g_A4p[(size_t)Bsz*T*E*C];      // comb hi  [b]

__device__ __forceinline__ unsigned smem_u32(const void* p) {
    unsigned a;
    asm("{ .reg .u64 t; cvta.to.shared.u64 t, %1; cvt.u32.u64 %0, t; }" : "=r"(a) : "l"(p));
    return a;
}
__device__ __forceinline__ void split_h(float v, __half& h, __half& l) {
    h = __float2half_rn(v);
    l = __float2half_rn(v - __half2float(h));
}
__device__ __forceinline__ float gelu(float v) {
    return 0.5f * v * (1.0f + erff(v * 0.70710678118654752f));
}
__device__ __forceinline__ unsigned pack2h(float a, float b) {
    __half2 p; p.x = __float2half_rn(a); p.y = __float2half_rn(b);
    return *(unsigned*)&p;
}

__device__ __forceinline__ void mbar_init(unsigned a, unsigned cnt) {
    asm volatile("mbarrier.init.shared.b64 [%0], %1;" :: "r"(a), "r"(cnt) : "memory");
}
__device__ __forceinline__ void mbar_arrive(unsigned a) {
    asm volatile("mbarrier.arrive.shared.b64 _, [%0];" :: "r"(a) : "memory");
}
__device__ __forceinline__ void mbar_expect_tx(unsigned a, unsigned bytes) {
    asm volatile("mbarrier.arrive.expect_tx.shared.b64 _, [%0], %1;"
                 :: "r"(a), "r"(bytes) : "memory");
}
__device__ __forceinline__ void mbar_wait(unsigned a, unsigned par) {
    asm volatile("{\n\t.reg .pred P;\n"
                 "WL%=:\n\t"
                 "mbarrier.try_wait.parity.acquire.cta.shared::cta.b64 P, [%0], %1, 0x989680;\n\t"
                 "@P bra.uni WD%=;\n\t"
                 "bra.uni WL%=;\n"
                 "WD%=:\n\t}" :: "r"(a), "r"(par) : "memory");
}
__device__ __forceinline__ void bulk_g2s(unsigned dst, const void* src,
                                         unsigned bytes, unsigned mbar) {
    asm volatile("cp.async.bulk.shared::cluster.global.mbarrier::complete_tx::bytes "
                 "[%0], [%1], %2, [%3];"
                 :: "r"(dst), "l"(src), "r"(bytes), "r"(mbar) : "memory");
}

#define LDSM_X4(R, addr) \
    asm volatile("ldmatrix.sync.aligned.m8n8.x4.shared.b16 {%0,%1,%2,%3}, [%4];" \
        : "=r"((R)[0]), "=r"((R)[1]), "=r"((R)[2]), "=r"((R)[3]) : "r"(addr))

#define MMA_F16(Cc, Aa, Bb) \
    asm volatile("mma.sync.aligned.m16n8k16.row.col.f32.f16.f16.f32 " \
        "{%0,%1,%2,%3}, {%4,%5,%6,%7}, {%8,%9}, {%0,%1,%2,%3};" \
        : "+f"((Cc)[0]), "+f"((Cc)[1]), "+f"((Cc)[2]), "+f"((Cc)[3]) \
        : "r"((Aa)[0]), "r"((Aa)[1]), "r"((Aa)[2]), "r"((Aa)[3]), \
          "r"((Bb)[0]), "r"((Bb)[1]))

// ---------------- coalesced hi-only pack kernels ----------------
// transpose: out[m][k] = in[k][m]; grid (M/128, K/32, Z), block 256
__global__ void pack_hi_t(const float* __restrict__ inBase, unsigned short* __restrict__ outRaw,
                          int Kdim, int rs, long inZdiv, long inZmod, int zdiv, long outZ) {
    int z = blockIdx.z;
    const float* in = inBase + (long)(z / zdiv) * inZdiv + (long)(z % zdiv) * inZmod;
    __half* out = (__half*)outRaw + (long)z * outZ;
    __shared__ float t[32][132];
    const int m0 = blockIdx.x * 128, k0 = blockIdx.y * 32;
    const int tid = threadIdx.x;
    const int lr = tid >> 5, lc = (tid & 31) * 4;
    #pragma unroll
    for (int i = 0; i < 4; ++i) {
        float4 v = *(const float4*)&in[(long)(k0 + lr + 8*i) * rs + m0 + lc];
        t[lr + 8*i][lc] = v.x; t[lr + 8*i][lc+1] = v.y;
        t[lr + 8*i][lc+2] = v.z; t[lr + 8*i][lc+3] = v.w;
    }
    __syncthreads();
    const int m = tid >> 1, hf = tid & 1;
    const int mg = m0 + m;
    long blob = ((long)(mg >> 7) * (Kdim >> 5) + blockIdx.y) * 4096 + (mg & 127) * 32;
    const unsigned sw = (unsigned)((mg >> 1) & 3);
    unsigned w[4];
    #pragma unroll
    for (int q = 0; q < 4; ++q)
        w[q] = pack2h(t[hf*16 + q*2][m], t[hf*16 + q*2 + 1][m]);
    unsigned w2[4];
    #pragma unroll
    for (int q = 0; q < 4; ++q)
        w2[q] = pack2h(t[hf*16 + 8 + q*2][m], t[hf*16 + 8 + q*2 + 1][m]);
    const unsigned u0 = (unsigned)(hf * 2), u1 = u0 + 1;
    *(uint4*)(out + blob + ((u0 ^ sw) << 3)) = make_uint4(w[0], w[1], w[2], w[3]);
    *(uint4*)(out + blob + ((u1 ^ sw) << 3)) = make_uint4(w2[0], w2[1], w2[2], w2[3]);
}

// no transpose: in [R, Kdim] fp32 row-major; one 8-half unit per thread
__global__ void pack_hi_nt(const float* __restrict__ in, unsigned short* __restrict__ outRaw,
                           long nUnits, int Kdim) {
    long i = (long)blockIdx.x * blockDim.x + threadIdx.x;
    if (i >= nUnits) return;
    const int upr = Kdim >> 3;
    long r = i / upr; int uq = (int)(i % upr);
    int g = uq >> 2, u = uq & 3;
    const float* src = in + r * Kdim + g * 32 + u * 8;
    float4 a = *(const float4*)src, b = *(const float4*)(src + 4);
    __half* out = (__half*)outRaw;
    long blob = ((r >> 7) * (long)(Kdim >> 5) + g) * 4096 + (r & 127) * 32;
    unsigned sw = (unsigned)((r >> 1) & 3);
    *(uint4*)(out + blob + ((((unsigned)u) ^ sw) << 3)) =
        make_uint4(pack2h(a.x, a.y), pack2h(a.z, a.w), pack2h(b.x, b.y), pack2h(b.z, b.w));
}

// ------- mma.sync fp16 GEMM, TMA-bulk fills, mbarrier ring -------
// ALO=1: C = (A_hi + A_lo) * B_hi ; ALO=0: C = A_hi * B_hi
// EPI: 0 = packed full hi/lo out; 1 = + bias + GELU; 2 = fp32 out; 3 = fp32 out + bias
template <int EPI, int ALO, int NSTG>
__global__ __launch_bounds__(256, 2)
void bgemm(const unsigned short* __restrict__ Ap,
           const unsigned short* __restrict__ Bp,
           void* __restrict__ Cout,
           const float* __restrict__ biasBase,
           int K, int Nn, int ldc,
           long Az, long Bz, long Cz, long biasZ, int bDiv)
{
    constexpr int ATB = ALO ? 16384 : 8192;
    constexpr int STB = ATB + 8192;
    extern __shared__ char dynsm[];
    __shared__ __align__(8) unsigned long long s_full[NSTG], s_empty[NSTG];
    const unsigned smBase = (smem_u32(dynsm) + 1023u) & ~1023u;

    const int tid  = threadIdx.x;
    const int z    = blockIdx.z;
    const int bIdx = (z / bDiv) % E;
    const int crow = blockIdx.y * 128;
    const int ccol = blockIdx.x * 128;

    const int lane = tid & 31;
    const int warp = tid >> 5;
    const int wm   = warp & 3;
    const int wn   = warp >> 2;
    const int gid  = lane >> 2, tig = lane & 3;
    const int nch  = K / 32;

    unsigned fullB[NSTG], emptyB[NSTG];
    #pragma unroll
    for (int s = 0; s < NSTG; ++s) {
        fullB[s]  = smem_u32(&s_full[s]);
        emptyB[s] = smem_u32(&s_empty[s]);
    }
    if (tid == 0) {
        #pragma unroll
        for (int s = 0; s < NSTG; ++s) { mbar_init(fullB[s], 1); mbar_init(emptyB[s], 8); }
    }
    __syncthreads();

    const char* gA = (const char*)(Ap + (long)z * Az) + (long)blockIdx.y * nch * ATB;
    const char* gB = (const char*)(Bp + (long)bIdx * Bz) + (long)blockIdx.x * nch * 8192;

    if (tid == 0) {
        #pragma unroll
        for (int tc = 0; tc < NSTG - 1; ++tc) {
            mbar_expect_tx(fullB[tc], STB);
            bulk_g2s(smBase + tc * STB,       gA + (long)tc * ATB, ATB,  fullB[tc]);
            bulk_g2s(smBase + tc * STB + ATB, gB + (long)tc * 8192, 8192, fullB[tc]);
        }
    }

    float acc[2][8][4];
    #pragma unroll
    for (int a = 0; a < 2; ++a)
        #pragma unroll
        for (int b = 0; b < 8; ++b)
            #pragma unroll
            for (int q = 0; q < 4; ++q) acc[a][b][q] = 0.0f;

    int cs = 0, cp = 0;                 // consumer stage/parity
    int pts = NSTG - 1, pq = 0;         // producer stage / parity of tc/NSTG

    for (int c = 0; c < nch; ++c) {
        if (tid == 0) {
            const int tc = c + NSTG - 1;
            if (tc < nch) {
                if (tc >= NSTG) mbar_wait(emptyB[pts], pq ^ 1);
                mbar_expect_tx(fullB[pts], STB);
                bulk_g2s(smBase + pts * STB,       gA + (long)tc * ATB, ATB,  fullB[pts]);
                bulk_g2s(smBase + pts * STB + ATB, gB + (long)tc * 8192, 8192, fullB[pts]);
                if (++pts == NSTG) { pts = 0; pq ^= 1; }
            }
        }
        mbar_wait(fullB[cs], cp);

        const unsigned aB = smBase + cs * STB;
        const unsigned bB = aB + ATB;

        #pragma unroll
        for (int ks = 0; ks < 2; ++ks) {
            unsigned aH[2][4], aL[2][4];
            #pragma unroll
            for (int mt = 0; mt < 2; ++mt) {
                unsigned r = wm * 32 + mt * 16 + (lane & 15);
                if (ALO) {
                    unsigned ca = (unsigned)(lane >> 4);
                    LDSM_X4(aH[mt], aB + r * 128 + ((((unsigned)(ks*2) + ca) ^ (r & 7)) << 4));
                    LDSM_X4(aL[mt], aB + r * 128 + ((((unsigned)(4 + ks*2) + ca) ^ (r & 7)) << 4));
                } else {
                    unsigned cu = (unsigned)(ks * 2 + (lane >> 4));
                    LDSM_X4(aH[mt], aB + r * 64 + ((cu ^ ((r >> 1) & 3)) << 4));
                }
            }
            #pragma unroll
            for (int p = 0; p < 4; ++p) {
                unsigned bH[4];
                unsigned r = wn * 64 + p * 16 + (lane & 7) + ((lane >> 4) << 3);
                unsigned cu = (unsigned)(ks * 2 + ((lane >> 3) & 1));
                LDSM_X4(bH, bB + r * 64 + ((cu ^ ((r >> 1) & 3)) << 4));
                #pragma unroll
                for (int mt = 0; mt < 2; ++mt)
                    #pragma unroll
                    for (int s2 = 0; s2 < 2; ++s2) {
                        float* cc = acc[mt][p * 2 + s2];
                        MMA_F16(cc, aH[mt], bH + 2 * s2);
                        if (ALO) MMA_F16(cc, aL[mt], bH + 2 * s2);
                    }
            }
        }
        if (lane == 0) mbar_arrive(emptyB[cs]);
        if (++cs == NSTG) { cs = 0; cp ^= 1; }
    }

    // ---- epilogue ----
    const float* bias = (EPI == 1 || EPI == 3) ? (biasBase + (long)bIdx * biasZ) : nullptr;

    #pragma unroll
    for (int mt = 0; mt < 2; ++mt) {
        #pragma unroll
        for (int half = 0; half < 2; ++half) {
            const int r = crow + wm * 32 + mt * 16 + gid + 8 * half;
            if (EPI <= 1) {
                unsigned short* dstz = (unsigned short*)Cout + (long)z * Cz;
                long rowBase = (long)(r >> 7) * (Nn >> 5) * 8192 + (long)(r & 127) * 64;
                const int ru = r & 7;
                #pragma unroll
                for (int nj = 0; nj < 8; ++nj) {
                    const int cg = ccol + wn * 64 + nj * 8 + 2 * tig;
                    float v0 = acc[mt][nj][2 * half];
                    float v1 = acc[mt][nj][2 * half + 1];
                    if (EPI == 1) {
                        v0 = gelu(v0 + bias[cg]);
                        v1 = gelu(v1 + bias[cg + 1]);
                    }
                    __half h0, l0, h1, l1;
                    split_h(v0, h0, l0); split_h(v1, h1, l1);
                    __half2 ph; ph.x = h0; ph.y = h1;
                    __half2 pl; pl.x = l0; pl.y = l1;
                    const int g = cg >> 5, j = cg & 31;
                    long tb = rowBase + (long)g * 8192;
                    int u0 = j >> 3;
                    int jp0 = (((u0 ^ ru) & 7) << 3) | (j & 7);
                    int u1 = 4 + u0;
                    int jp1 = (((u1 ^ ru) & 7) << 3) | (j & 7);
                    *(__half2*)(dstz + tb + jp0) = ph;
                    *(__half2*)(dstz + tb + jp1) = pl;
                }
            } else {
                float* dst = (float*)Cout + (long)z * Cz + (long)r * ldc;
                #pragma unroll
                for (int nj = 0; nj < 8; ++nj) {
                    const int cg = ccol + wn * 64 + nj * 8 + 2 * tig;
                    float v0 = acc[mt][nj][2 * half];
                    float v1 = acc[mt][nj][2 * half + 1];
                    if (EPI == 3) { v0 += bias[cg]; v1 += bias[cg + 1]; }
                    float2 p; p.x = v0; p.y = v1;
                    *(float2*)(dst + cg) = p;
                }
            }
        }
    }
}

} // namespace

extern "C" void kernel_launch(void* const* d_in, const int* in_sizes, int n_in,
                              void* d_out, int out_size)
{
    const float* x    = (const float*)d_in[0];
    const float* dm   = (const float*)d_in[1];
    const float* comb = (const float*)d_in[2];
    const float* w1   = (const float*)d_in[3];
    const float* b1   = (const float*)d_in[4];
    const float* w2   = (const float*)d_in[5];
    const float* b2   = (const float*)d_in[6];
    float* out = (float*)d_out;

    unsigned short *A1p, *B1p, *B2p, *B3p, *A2p, *A3p, *B4p, *A4p;
    float* yscr;
    cudaGetSymbolAddress((void**)&A1p, g_A1p);
    cudaGetSymbolAddress((void**)&B1p, g_B1p);
    cudaGetSymbolAddress((void**)&B2p, g_B2p);
    cudaGetSymbolAddress((void**)&B3p, g_B3p);
    cudaGetSymbolAddress((void**)&A2p, g_A2p);
    cudaGetSymbolAddress((void**)&A3p, g_A3p);
    cudaGetSymbolAddress((void**)&B4p, g_B4p);
    cudaGetSymbolAddress((void**)&A4p, g_A4p);
    cudaGetSymbolAddress((void**)&yscr, g_y);

    cudaFuncSetAttribute(bgemm<0,0,6>, cudaFuncAttributeMaxDynamicSharedMemorySize, SMEM_DYN);
    cudaFuncSetAttribute(bgemm<1,1,4>, cudaFuncAttributeMaxDynamicSharedMemorySize, SMEM_DYN);
    cudaFuncSetAttribute(bgemm<2,1,4>, cudaFuncAttributeMaxDynamicSharedMemorySize, SMEM_DYN);
    cudaFuncSetAttribute(bgemm<3,0,6>, cudaFuncAttributeMaxDynamicSharedMemorySize, SMEM_DYN);

    // #1 dm^T -> A1p (hi): per (b,e)
    pack_hi_t<<<dim3(C/128, T/32, Bsz*E), 256>>>(dm, A1p, T, E*C,
        (long)T*E*C, (long)C, E, (long)C*T);
    // #2 x^T -> B1p (hi): per b
    pack_hi_t<<<dim3(D/128, T/32, Bsz), 256>>>(x, B1p, T, D,
        (long)T*D, 0L, 1, (long)D*T);
    // #3 w1^T -> B2p (hi): per e
    pack_hi_t<<<dim3(HE/128, D/32, E), 256>>>(w1, B2p, D, HE,
        (long)D*HE, 0L, 1, (long)HE*D);
    // #4 S1: xd = dm^T * x  (M=C, N=D, K=T) -> A2p (full)   [profiled slot]
    bgemm<0,0,6><<<dim3(D/128, C/128, Bsz*E), 256, SMEM_DYN>>>(
        A1p, B1p, A2p, nullptr, T, D, D,
        (long)C*T, (long)D*T, (long)C*2*D, 0L, 4);
    // #5 w2^T -> B3p (hi): per e
    pack_hi_t<<<dim3(O/128, HE/32, E), 256>>>(w2, B3p, HE, O,
        (long)HE*O, 0L, 1, (long)O*HE);
    // #6 comb -> A4p (hi)
    {
        long nUnits = (long)Bsz * T * E * C / 8;
        pack_hi_nt<<<(unsigned)((nUnits + 255) / 256), 256>>>(comb, A4p, nUnits, E*C);
    }
    // #7 S2: h = gelu(xd*w1 + b1)  (K=D) -> A3p (full)
    bgemm<1,1,4><<<dim3(HE/128, C/128, Bsz*E), 256, SMEM_DYN>>>(
        A2p, B2p, A3p, b1, D, HE, HE,
        (long)C*2*D, (long)HE*D, (long)C*2*HE, (long)HE, 1);
    // #8 S3: y = h*w2  (K=HE) fp32 -> yscr
    bgemm<2,1,4><<<dim3(O/128, C/128, Bsz*E), 256, SMEM_DYN>>>(
        A3p, B3p, yscr, nullptr, HE, O, O,
        (long)C*2*HE, (long)O*HE, (long)C*O, 0L, 1);
    // #9 y^T -> B4p (hi): per b
    pack_hi_t<<<dim3(O/128, (E*C)/32, Bsz), 256>>>(yscr, B4p, E*C, O,
        (long)E*C*O, 0L, 1, (long)O*E*C);
    // #10 S4: out = comb * y^T + b2  (M=T, N=O, K=EC) fp32 out
    bgemm<3,0,6><<<dim3(O/128, T/128, Bsz), 256, SMEM_DYN>>>(
        A4p, B4p, out, b2, E*C, O, O,
        (long)T*E*C, (long)O*E*C, (long)T*O, 0L, 1);
}

// round 10
// speedup vs baseline: 6.3254x; 1.0724x over previous
#include <cuda_runtime.h>
#include <cuda_fp16.h>
#include <math.h>

namespace {

constexpr int Bsz = 4, T = 2048, D = 512, E = 4, C = 1024, HE = 512, O = 512;
constexpr int SMEM_DYN = 98304 + 1024;
constexpr int GMAX = 296;   // 148 SMs x 2 CTAs

// hi-only operands: blob per (128-row mtile, 32-k chunk):
//   [row 0..127][32 halfs; 16B-unit u in 0..3 at u^((row>>1)&3)]  (4096 halfs)
// full hi/lo operands (GEMM-epilogue-produced):
//   [row 0..127][64 halfs = 32hi|32lo; 16B-unit u in 0..7 at u^(row&7)] (8192 halfs)
__device__ __align__(256) unsigned short g_A1p[(size_t)Bsz*E*C*T];      // dm^T hi  [be]
__device__ __align__(256) unsigned short g_B1p[(size_t)Bsz*D*T];        // x^T  hi  [b]
__device__ __align__(256) unsigned short g_B2p[(size_t)E*HE*D];         // w1^T hi  [e]
__device__ __align__(256) unsigned short g_B3p[(size_t)E*O*HE];         // w2^T hi  [e]
__device__ __align__(256) unsigned short g_A2p[(size_t)Bsz*E*C*2*D];    // xd  full [be]
__device__ __align__(256) unsigned short g_A3p[(size_t)Bsz*E*C*2*HE];   // h   full [be]
__device__ __align__(256) float          g_y  [(size_t)Bsz*E*C*O];      // fp32 y
__device__ __align__(256) unsigned short g_B4p[(size_t)Bsz*O*E*C];      // y^T  hi  [b]
__device__ __align__(256) unsigned short g_A4p[(size_t)Bsz*T*E*C];      // comb hi  [b]

__device__ __forceinline__ unsigned smem_u32(const void* p) {
    unsigned a;
    asm("{ .reg .u64 t; cvta.to.shared.u64 t, %1; cvt.u32.u64 %0, t; }" : "=r"(a) : "l"(p));
    return a;
}
__device__ __forceinline__ void split_h(float v, __half& h, __half& l) {
    h = __float2half_rn(v);
    l = __float2half_rn(v - __half2float(h));
}
__device__ __forceinline__ float gelu(float v) {
    return 0.5f * v * (1.0f + erff(v * 0.70710678118654752f));
}
__device__ __forceinline__ unsigned pack2h(float a, float b) {
    __half2 p; p.x = __float2half_rn(a); p.y = __float2half_rn(b);
    return *(unsigned*)&p;
}

__device__ __forceinline__ void mbar_init(unsigned a, unsigned cnt) {
    asm volatile("mbarrier.init.shared.b64 [%0], %1;" :: "r"(a), "r"(cnt) : "memory");
}
__device__ __forceinline__ void mbar_arrive(unsigned a) {
    asm volatile("mbarrier.arrive.shared.b64 _, [%0];" :: "r"(a) : "memory");
}
__device__ __forceinline__ void mbar_expect_tx(unsigned a, unsigned bytes) {
    asm volatile("mbarrier.arrive.expect_tx.shared.b64 _, [%0], %1;"
                 :: "r"(a), "r"(bytes) : "memory");
}
__device__ __forceinline__ void mbar_wait(unsigned a, unsigned par) {
    asm volatile("{\n\t.reg .pred P;\n"
                 "WL%=:\n\t"
                 "mbarrier.try_wait.parity.acquire.cta.shared::cta.b64 P, [%0], %1, 0x989680;\n\t"
                 "@P bra.uni WD%=;\n\t"
                 "bra.uni WL%=;\n"
                 "WD%=:\n\t}" :: "r"(a), "r"(par) : "memory");
}
__device__ __forceinline__ void bulk_g2s(unsigned dst, const void* src,
                                         unsigned bytes, unsigned mbar) {
    asm volatile("cp.async.bulk.shared::cluster.global.mbarrier::complete_tx::bytes "
                 "[%0], [%1], %2, [%3];"
                 :: "r"(dst), "l"(src), "r"(bytes), "r"(mbar) : "memory");
}

#define LDSM_X4(R, addr) \
    asm volatile("ldmatrix.sync.aligned.m8n8.x4.shared.b16 {%0,%1,%2,%3}, [%4];" \
        : "=r"((R)[0]), "=r"((R)[1]), "=r"((R)[2]), "=r"((R)[3]) : "r"(addr))

#define MMA_F16(Cc, Aa, Bb) \
    asm volatile("mma.sync.aligned.m16n8k16.row.col.f32.f16.f16.f32 " \
        "{%0,%1,%2,%3}, {%4,%5,%6,%7}, {%8,%9}, {%0,%1,%2,%3};" \
        : "+f"((Cc)[0]), "+f"((Cc)[1]), "+f"((Cc)[2]), "+f"((Cc)[3]) \
        : "r"((Aa)[0]), "r"((Aa)[1]), "r"((Aa)[2]), "r"((Aa)[3]), \
          "r"((Bb)[0]), "r"((Bb)[1]))

// ---------------- coalesced hi-only pack kernels ----------------
__global__ void pack_hi_t(const float* __restrict__ inBase, unsigned short* __restrict__ outRaw,
                          int Kdim, int rs, long inZdiv, long inZmod, int zdiv, long outZ) {
    int z = blockIdx.z;
    const float* in = inBase + (long)(z / zdiv) * inZdiv + (long)(z % zdiv) * inZmod;
    __half* out = (__half*)outRaw + (long)z * outZ;
    __shared__ float t[32][132];
    const int m0 = blockIdx.x * 128, k0 = blockIdx.y * 32;
    const int tid = threadIdx.x;
    const int lr = tid >> 5, lc = (tid & 31) * 4;
    #pragma unroll
    for (int i = 0; i < 4; ++i) {
        float4 v = *(const float4*)&in[(long)(k0 + lr + 8*i) * rs + m0 + lc];
        t[lr + 8*i][lc] = v.x; t[lr + 8*i][lc+1] = v.y;
        t[lr + 8*i][lc+2] = v.z; t[lr + 8*i][lc+3] = v.w;
    }
    __syncthreads();
    const int m = tid >> 1, hf = tid & 1;
    const int mg = m0 + m;
    long blob = ((long)(mg >> 7) * (Kdim >> 5) + blockIdx.y) * 4096 + (mg & 127) * 32;
    const unsigned sw = (unsigned)((mg >> 1) & 3);
    unsigned w[4], w2[4];
    #pragma unroll
    for (int q = 0; q < 4; ++q)
        w[q] = pack2h(t[hf*16 + q*2][m], t[hf*16 + q*2 + 1][m]);
    #pragma unroll
    for (int q = 0; q < 4; ++q)
        w2[q] = pack2h(t[hf*16 + 8 + q*2][m], t[hf*16 + 8 + q*2 + 1][m]);
    const unsigned u0 = (unsigned)(hf * 2), u1 = u0 + 1;
    *(uint4*)(out + blob + ((u0 ^ sw) << 3)) = make_uint4(w[0], w[1], w[2], w[3]);
    *(uint4*)(out + blob + ((u1 ^ sw) << 3)) = make_uint4(w2[0], w2[1], w2[2], w2[3]);
}

__global__ void pack_hi_nt(const float* __restrict__ in, unsigned short* __restrict__ outRaw,
                           long nUnits, int Kdim) {
    long i = (long)blockIdx.x * blockDim.x + threadIdx.x;
    if (i >= nUnits) return;
    const int upr = Kdim >> 3;
    long r = i / upr; int uq = (int)(i % upr);
    int g = uq >> 2, u = uq & 3;
    const float* src = in + r * Kdim + g * 32 + u * 8;
    float4 a = *(const float4*)src, b = *(const float4*)(src + 4);
    __half* out = (__half*)outRaw;
    long blob = ((r >> 7) * (long)(Kdim >> 5) + g) * 4096 + (r & 127) * 32;
    unsigned sw = (unsigned)((r >> 1) & 3);
    *(uint4*)(out + blob + ((((unsigned)u) ^ sw) << 3)) =
        make_uint4(pack2h(a.x, a.y), pack2h(a.z, a.w), pack2h(b.x, b.y), pack2h(b.z, b.w));
}

// ------- persistent mma.sync fp16 GEMM, TMA-bulk fills, continuous producer -------
// ALO=1: C = (A_hi + A_lo) * B_hi ; ALO=0: C = A_hi * B_hi
// EPI: 0 = packed full hi/lo out; 1 = + bias + GELU; 2 = fp32 out; 3 = fp32 out + bias
template <int EPI, int ALO, int KG, int NSTG>
__global__ __launch_bounds__(256, 2)
void bgemm(const unsigned short* __restrict__ Ap,
           const unsigned short* __restrict__ Bp,
           void* __restrict__ Cout,
           const float* __restrict__ biasBase,
           int K, int Nn, int ldc,
           long Az, long Bz, long Cz, long biasZ,
           int bDiv, int tX, int tXY, int nTiles)
{
    constexpr int ATB = ALO ? 16384 : 8192;
    constexpr int BTB = 8192;
    constexpr int STB = KG * (ATB + BTB);
    extern __shared__ char dynsm[];
    __shared__ __align__(8) unsigned long long s_full[NSTG], s_empty[NSTG];

    const int bid = blockIdx.x, G = gridDim.x;
    if (bid >= nTiles) return;
    const unsigned smBase = (smem_u32(dynsm) + 1023u) & ~1023u;

    const int tid  = threadIdx.x;
    const int lane = tid & 31;
    const int warp = tid >> 5;
    const int wm   = warp & 3;
    const int wn   = warp >> 2;
    const int gid  = lane >> 2, tig = lane & 3;

    const int nch = K / 32, spt = nch / KG;
    const int myTiles  = (nTiles - bid + G - 1) / G;
    const int myStages = myTiles * spt;

    unsigned fullB[NSTG], emptyB[NSTG];
    #pragma unroll
    for (int s = 0; s < NSTG; ++s) {
        fullB[s]  = smem_u32(&s_full[s]);
        emptyB[s] = smem_u32(&s_empty[s]);
    }
    if (tid == 0) {
        #pragma unroll
        for (int s = 0; s < NSTG; ++s) { mbar_init(fullB[s], 1); mbar_init(emptyB[s], 8); }
    }
    __syncthreads();

    // ---- producer state (continuous across tiles) ----
    int ptile = bid, pStage = 0, pslot = 0, pph = 0, pcount = 0;
    const char *pgA, *pgB;
    {
        int z = ptile / tXY, r0 = ptile - z * tXY, ty = r0 / tX, tx = r0 - ty * tX;
        pgA = (const char*)(Ap + (long)z * Az) + (long)ty * nch * ATB;
        pgB = (const char*)(Bp + (long)((z / bDiv) % E) * Bz) + (long)tx * nch * BTB;
    }

    auto produce = [&]() {
        if (tid == 0) {
            if (pcount >= NSTG) mbar_wait(emptyB[pslot], pph ^ 1);
            mbar_expect_tx(fullB[pslot], STB);
            bulk_g2s(smBase + pslot * STB,          pgA + (long)pStage * (KG * ATB), KG * ATB, fullB[pslot]);
            bulk_g2s(smBase + pslot * STB + KG*ATB, pgB + (long)pStage * (KG * BTB), KG * BTB, fullB[pslot]);
        }
        ++pcount;
        if (++pslot == NSTG) { pslot = 0; pph ^= 1; }
        if (++pStage == spt) {
            pStage = 0; ptile += G;
            if (ptile < nTiles) {
                int z = ptile / tXY, r0 = ptile - z * tXY, ty = r0 / tX, tx = r0 - ty * tX;
                pgA = (const char*)(Ap + (long)z * Az) + (long)ty * nch * ATB;
                pgB = (const char*)(Bp + (long)((z / bDiv) % E) * Bz) + (long)tx * nch * BTB;
            }
        }
    };

    for (int i = 0; i < NSTG - 1 && i < myStages; ++i) produce();

    float acc[2][8][4];
    #pragma unroll
    for (int a = 0; a < 2; ++a)
        #pragma unroll
        for (int b = 0; b < 8; ++b)
            #pragma unroll
            for (int q = 0; q < 4; ++q) acc[a][b][q] = 0.0f;

    int cs = 0, cp = 0, cKg = 0, ctile = bid;

    for (int s = 0; s < myStages; ++s) {
        if (s + NSTG - 1 < myStages) produce();
        mbar_wait(fullB[cs], cp);

        const unsigned stg = smBase + cs * STB;
        #pragma unroll
        for (int kg = 0; kg < KG; ++kg) {
            const unsigned aB = stg + kg * ATB;
            const unsigned bB = stg + KG * ATB + kg * BTB;
            #pragma unroll
            for (int ks = 0; ks < 2; ++ks) {
                unsigned aH[2][4], aL[2][4];
                #pragma unroll
                for (int mt = 0; mt < 2; ++mt) {
                    unsigned r = wm * 32 + mt * 16 + (lane & 15);
                    if (ALO) {
                        unsigned ca = (unsigned)(lane >> 4);
                        LDSM_X4(aH[mt], aB + r * 128 + ((((unsigned)(ks*2) + ca) ^ (r & 7)) << 4));
                        LDSM_X4(aL[mt], aB + r * 128 + ((((unsigned)(4 + ks*2) + ca) ^ (r & 7)) << 4));
                    } else {
                        unsigned cu = (unsigned)(ks * 2 + (lane >> 4));
                        LDSM_X4(aH[mt], aB + r * 64 + ((cu ^ ((r >> 1) & 3)) << 4));
                    }
                }
                #pragma unroll
                for (int p = 0; p < 4; ++p) {
                    unsigned bH[4];
                    unsigned r = wn * 64 + p * 16 + (lane & 7) + ((lane >> 4) << 3);
                    unsigned cu = (unsigned)(ks * 2 + ((lane >> 3) & 1));
                    LDSM_X4(bH, bB + r * 64 + ((cu ^ ((r >> 1) & 3)) << 4));
                    #pragma unroll
                    for (int mt = 0; mt < 2; ++mt)
                        #pragma unroll
                        for (int s2 = 0; s2 < 2; ++s2) {
                            float* cc = acc[mt][p * 2 + s2];
                            MMA_F16(cc, aH[mt], bH + 2 * s2);
                            if (ALO) MMA_F16(cc, aL[mt], bH + 2 * s2);
                        }
                }
            }
        }
        if (lane == 0) mbar_arrive(emptyB[cs]);
        if (++cs == NSTG) { cs = 0; cp ^= 1; }

        if (++cKg == spt) {
            // ---- epilogue for ctile (producer already prefetching next tile) ----
            int z = ctile / tXY, r0 = ctile - z * tXY, ty = r0 / tX, tx = r0 - ty * tX;
            const int crow = ty * 128, ccol = tx * 128;
            const int bIdx = (z / bDiv) % E;
            const float* bias = (EPI == 1 || EPI == 3) ? (biasBase + (long)bIdx * biasZ) : nullptr;

            #pragma unroll
            for (int mt = 0; mt < 2; ++mt) {
                #pragma unroll
                for (int half = 0; half < 2; ++half) {
                    const int r = crow + wm * 32 + mt * 16 + gid + 8 * half;
                    if (EPI <= 1) {
                        unsigned short* dstz = (unsigned short*)Cout + (long)z * Cz;
                        long rowBase = (long)(r >> 7) * (Nn >> 5) * 8192 + (long)(r & 127) * 64;
                        const int ru = r & 7;
                        #pragma unroll
                        for (int nj = 0; nj < 8; ++nj) {
                            const int cg = ccol + wn * 64 + nj * 8 + 2 * tig;
                            float v0 = acc[mt][nj][2 * half];
                            float v1 = acc[mt][nj][2 * half + 1];
                            if (EPI == 1) {
                                v0 = gelu(v0 + bias[cg]);
                                v1 = gelu(v1 + bias[cg + 1]);
                            }
                            __half h0, l0, h1, l1;
                            split_h(v0, h0, l0); split_h(v1, h1, l1);
                            __half2 ph; ph.x = h0; ph.y = h1;
                            __half2 pl; pl.x = l0; pl.y = l1;
                            const int g = cg >> 5, j = cg & 31;
                            long tb = rowBase + (long)g * 8192;
                            int u0 = j >> 3;
                            int jp0 = (((u0 ^ ru) & 7) << 3) | (j & 7);
                            int u1 = 4 + u0;
                            int jp1 = (((u1 ^ ru) & 7) << 3) | (j & 7);
                            *(__half2*)(dstz + tb + jp0) = ph;
                            *(__half2*)(dstz + tb + jp1) = pl;
                        }
                    } else {
                        float* dst = (float*)Cout + (long)z * Cz + (long)r * ldc;
                        #pragma unroll
                        for (int nj = 0; nj < 8; ++nj) {
                            const int cg = ccol + wn * 64 + nj * 8 + 2 * tig;
                            float v0 = acc[mt][nj][2 * half];
                            float v1 = acc[mt][nj][2 * half + 1];
                            if (EPI == 3) { v0 += bias[cg]; v1 += bias[cg + 1]; }
                            float2 p; p.x = v0; p.y = v1;
                            *(float2*)(dst + cg) = p;
                        }
                    }
                }
            }
            cKg = 0; ctile += G;
            #pragma unroll
            for (int a = 0; a < 2; ++a)
                #pragma unroll
                for (int b = 0; b < 8; ++b)
                    #pragma unroll
                    for (int q = 0; q < 4; ++q) acc[a][b][q] = 0.0f;
        }
    }
}

} // namespace

extern "C" void kernel_launch(void* const* d_in, const int* in_sizes, int n_in,
                              void* d_out, int out_size)
{
    const float* x    = (const float*)d_in[0];
    const float* dm   = (const float*)d_in[1];
    const float* comb = (const float*)d_in[2];
    const float* w1   = (const float*)d_in[3];
    const float* b1   = (const float*)d_in[4];
    const float* w2   = (const float*)d_in[5];
    const float* b2   = (const float*)d_in[6];
    float* out = (float*)d_out;

    unsigned short *A1p, *B1p, *B2p, *B3p, *A2p, *A3p, *B4p, *A4p;
    float* yscr;
    cudaGetSymbolAddress((void**)&A1p, g_A1p);
    cudaGetSymbolAddress((void**)&B1p, g_B1p);
    cudaGetSymbolAddress((void**)&B2p, g_B2p);
    cudaGetSymbolAddress((void**)&B3p, g_B3p);
    cudaGetSymbolAddress((void**)&A2p, g_A2p);
    cudaGetSymbolAddress((void**)&A3p, g_A3p);
    cudaGetSymbolAddress((void**)&B4p, g_B4p);
    cudaGetSymbolAddress((void**)&A4p, g_A4p);
    cudaGetSymbolAddress((void**)&yscr, g_y);

    cudaFuncSetAttribute(bgemm<0,0,2,3>, cudaFuncAttributeMaxDynamicSharedMemorySize, SMEM_DYN);
    cudaFuncSetAttribute(bgemm<1,1,1,4>, cudaFuncAttributeMaxDynamicSharedMemorySize, SMEM_DYN);
    cudaFuncSetAttribute(bgemm<2,1,1,4>, cudaFuncAttributeMaxDynamicSharedMemorySize, SMEM_DYN);
    cudaFuncSetAttribute(bgemm<3,0,2,3>, cudaFuncAttributeMaxDynamicSharedMemorySize, SMEM_DYN);

    // #1 dm^T -> A1p (hi): per (b,e)
    pack_hi_t<<<dim3(C/128, T/32, Bsz*E), 256>>>(dm, A1p, T, E*C,
        (long)T*E*C, (long)C, E, (long)C*T);
    // #2 x^T -> B1p (hi): per b
    pack_hi_t<<<dim3(D/128, T/32, Bsz), 256>>>(x, B1p, T, D,
        (long)T*D, 0L, 1, (long)D*T);
    // #3 w1^T -> B2p (hi): per e
    pack_hi_t<<<dim3(HE/128, D/32, E), 256>>>(w1, B2p, D, HE,
        (long)D*HE, 0L, 1, (long)HE*D);
    // #4 S1: xd = dm^T * x  (M=C, N=D, K=T) -> A2p (full)   [profiled slot]
    {
        int nT = (D/128) * (C/128) * (Bsz*E);   // 512
        bgemm<0,0,2,3><<<(nT < GMAX ? nT : GMAX), 256, SMEM_DYN>>>(
            A1p, B1p, A2p, nullptr, T, D, D,
            (long)C*T, (long)D*T, (long)C*2*D, 0L,
            4, D/128, (D/128)*(C/128), nT);
    }
    // #5 w2^T -> B3p (hi): per e
    pack_hi_t<<<dim3(O/128, HE/32, E), 256>>>(w2, B3p, HE, O,
        (long)HE*O, 0L, 1, (long)O*HE);
    // #6 comb -> A4p (hi)
    {
        long nUnits = (long)Bsz * T * E * C / 8;
        pack_hi_nt<<<(unsigned)((nUnits + 255) / 256), 256>>>(comb, A4p, nUnits, E*C);
    }
    // #7 S2: h = gelu(xd*w1 + b1)  (K=D) -> A3p (full)
    {
        int nT = (HE/128) * (C/128) * (Bsz*E);  // 512
        bgemm<1,1,1,4><<<(nT < GMAX ? nT : GMAX), 256, SMEM_DYN>>>(
            A2p, B2p, A3p, b1, D, HE, HE,
            (long)C*2*D, (long)HE*D, (long)C*2*HE, (long)HE,
            1, HE/128, (HE/128)*(C/128), nT);
    }
    // #8 S3: y = h*w2  (K=HE) fp32 -> yscr
    {
        int nT = (O/128) * (C/128) * (Bsz*E);   // 512
        bgemm<2,1,1,4><<<(nT < GMAX ? nT : GMAX), 256, SMEM_DYN>>>(
            A3p, B3p, yscr, nullptr, HE, O, O,
            (long)C*2*HE, (long)O*HE, (long)C*O, 0L,
            1, O/128, (O/128)*(C/128), nT);
    }
    // #9 y^T -> B4p (hi): per b
    pack_hi_t<<<dim3(O/128, (E*C)/32, Bsz), 256>>>(yscr, B4p, E*C, O,
        (long)E*C*O, 0L, 1, (long)O*E*C);
    // #10 S4: out = comb * y^T + b2  (M=T, N=O, K=EC) fp32 out
    {
        int nT = (O/128) * (T/128) * Bsz;       // 256
        bgemm<3,0,2,3><<<(nT < GMAX ? nT : GMAX), 256, SMEM_DYN>>>(
            A4p, B4p, out, b2, E*C, O, O,
            (long)T*E*C, (long)O*E*C, (long)T*O, 0L,
            1, O/128, (O/128)*(T/128), nT);
    }
}